// round 3
// baseline (speedup 1.0000x reference)
#include <cuda_runtime.h>
#include <math.h>

#define BATCH  32768
#define NWARPS 8
#define THREADS (NWARPS * 32)
#define NBLOCKS (BATCH / NWARPS)
#define MAXSWEEP 7

__device__ double g_pd[NBLOCKS][4];   // sum_eig, sum_s, sum_fro, sum_absO
__device__ float  g_pmx[NBLOCKS];
__device__ float  g_pmn[NBLOCKS];

// ---- packed f32x2 helpers (Blackwell FFMA2 path) ----
__device__ __forceinline__ unsigned long long pk2(float lo, float hi) {
    unsigned long long r;
    asm("mov.b64 %0, {%1, %2};" : "=l"(r) : "f"(lo), "f"(hi));
    return r;
}
__device__ __forceinline__ void upk2(unsigned long long v, float& lo, float& hi) {
    asm("mov.b64 {%0, %1}, %2;" : "=f"(lo), "=f"(hi) : "l"(v));
}
__device__ __forceinline__ unsigned long long fma2(unsigned long long a,
                                                   unsigned long long b,
                                                   unsigned long long c) {
    unsigned long long d;
    asm("fma.rn.f32x2 %0, %1, %2, %3;" : "=l"(d) : "l"(a), "l"(b), "l"(c));
    return d;
}
__device__ __forceinline__ unsigned long long mul2(unsigned long long a,
                                                   unsigned long long b) {
    unsigned long long d;
    asm("mul.rn.f32x2 %0, %1, %2;" : "=l"(d) : "l"(a), "l"(b));
    return d;
}

__global__ __launch_bounds__(THREADS)
void cond_main_kernel(const float* __restrict__ inp, const float* __restrict__ outp) {
    __shared__ float  Osh[NWARPS][625];
    __shared__ double redd[NWARPS][4];
    __shared__ float  redmx[NWARPS];
    __shared__ float  redmn[NWARPS];

    const int w    = threadIdx.x >> 5;
    const int lane = threadIdx.x & 31;
    const int b    = blockIdx.x * NWARPS + w;

    const float* O = outp + (size_t)b * 625;
    const float* I = inp  + (size_t)b * 625;
    float* Os = Osh[w];

    const bool act25 = (lane < 25);

    // Load O into smem (coalesced), accumulate sum|O|
    float absO = 0.f;
    for (int idx = lane; idx < 625; idx += 32) {
        float v = O[idx];
        absO += fabsf(v);
        Os[idx] = v;
    }
    // Column `lane` of I into registers
    float Icol[25];
    #pragma unroll
    for (int k = 0; k < 25; k++)
        Icol[k] = act25 ? I[k * 25 + lane] : 0.f;
    __syncwarp();

    // col = column `lane` of C = O @ I ; frosq partial of ||C - I||_F^2
    float col[25];
    float frosq = 0.f;
    #pragma unroll
    for (int i = 0; i < 25; i++) {
        float acc = 0.f;
        #pragma unroll
        for (int k = 0; k < 25; k++)
            acc = fmaf(Os[i * 25 + k], Icol[k], acc);
        col[i] = acc;
        float d = acc - ((i == lane) ? 1.f : 0.f);
        if (act25) frosq += d * d;
    }

    // Pack column into 13 f32x2 registers (last hi = 0 padding; rotations keep it 0)
    unsigned long long col2[13];
    #pragma unroll
    for (int k = 0; k < 12; k++) col2[k] = pk2(col[2 * k], col[2 * k + 1]);
    col2[12] = pk2(col[24], 0.f);

    // One-sided (Hestenes) Jacobi, register-resident, packed f32x2.
    // Round r: lane x pairs with (2r - x) mod 25.
    for (int sweep = 0; sweep < MAXSWEEP; sweep++) {
        bool conv = true;
        for (int r = 0; r < 25; r++) {
            int partner = 2 * r - lane;
            partner %= 25;
            if (partner < 0) partner += 25;
            const bool active = act25 && (partner != lane);

            unsigned long long o2[13];
            unsigned long long a2 = 0ull, g2 = 0ull;
            #pragma unroll
            for (int i = 0; i < 13; i++) {
                o2[i] = __shfl_sync(0xffffffffu, col2[i], partner);
                a2 = fma2(col2[i], col2[i], a2);
                g2 = fma2(col2[i], o2[i], g2);
            }
            float al, ah, gl, gh;
            upk2(a2, al, ah);
            upk2(g2, gl, gh);
            float alpha = al + ah;
            float gam   = gl + gh;
            float alpha_o = __shfl_sync(0xffffffffu, alpha, partner);

            float c = 1.f, s = 0.f;
            if (active && fabsf(gam) > 1e-28f) {
                float zeta = __fdividef(alpha_o - alpha, 2.f * gam);
                float t = __fdividef(1.f, fabsf(zeta) + sqrtf(fmaf(zeta, zeta, 1.f)));
                t = copysignf(t, zeta);
                c = rsqrtf(fmaf(t, t, 1.f));
                s = t * c;
            }
            if (active)
                conv = conv && (gam * gam <= 1e-6f * alpha * alpha_o);

            unsigned long long cc2 = pk2(c, c);
            unsigned long long ns2 = pk2(-s, -s);
            #pragma unroll
            for (int i = 0; i < 13; i++)
                col2[i] = fma2(cc2, col2[i], mul2(ns2, o2[i]));
        }
        if (__all_sync(0xffffffffu, conv)) break;
    }

    // Singular values: S_j^2 = ||col_j||^2
    unsigned long long a2 = 0ull;
    #pragma unroll
    for (int i = 0; i < 13; i++) a2 = fma2(col2[i], col2[i], a2);
    float al, ah;
    upk2(a2, al, ah);
    float alpha = al + ah;

    float ac   = fmaxf(alpha, 1e-12f);
    float Sv   = sqrtf(alpha);
    float suma = act25 ? alpha : 0.f;
    float sums = act25 ? Sv : 0.f;
    float mxa  = act25 ? ac : 0.f;
    float mna  = act25 ? ac : 3.0e38f;

    #pragma unroll
    for (int off = 16; off > 0; off >>= 1) {
        suma  += __shfl_xor_sync(0xffffffffu, suma, off);
        sums  += __shfl_xor_sync(0xffffffffu, sums, off);
        frosq += __shfl_xor_sync(0xffffffffu, frosq, off);
        absO  += __shfl_xor_sync(0xffffffffu, absO, off);
        mxa = fmaxf(mxa, __shfl_xor_sync(0xffffffffu, mxa, off));
        mna = fminf(mna, __shfl_xor_sync(0xffffffffu, mna, off));
    }
    if (lane == 0) {
        redd[w][0] = (double)suma;
        redd[w][1] = (double)sums;
        redd[w][2] = (double)sqrtf(frosq);
        redd[w][3] = (double)absO;
        redmx[w] = mxa;
        redmn[w] = mna;
    }
    __syncthreads();

    if (threadIdx.x == 0) {
        double a0 = 0.0, a1 = 0.0, s2 = 0.0, a3 = 0.0;
        float mx = 0.f, mn = 3.0e38f;
        #pragma unroll
        for (int i = 0; i < NWARPS; i++) {
            a0 += redd[i][0]; a1 += redd[i][1]; s2 += redd[i][2]; a3 += redd[i][3];
            mx = fmaxf(mx, redmx[i]);
            mn = fminf(mn, redmn[i]);
        }
        g_pd[blockIdx.x][0] = a0;
        g_pd[blockIdx.x][1] = a1;
        g_pd[blockIdx.x][2] = s2;
        g_pd[blockIdx.x][3] = a3;
        g_pmx[blockIdx.x] = mx;
        g_pmn[blockIdx.x] = mn;
    }
}

__global__ __launch_bounds__(256)
void cond_final_kernel(float* __restrict__ out) {
    __shared__ double sd[256][4];
    __shared__ float  smx[256];
    __shared__ float  smn[256];

    const int t = threadIdx.x;
    double a0 = 0.0, a1 = 0.0, a2 = 0.0, a3 = 0.0;
    float mx = 0.f, mn = 3.0e38f;
    for (int i = t; i < NBLOCKS; i += 256) {
        a0 += g_pd[i][0]; a1 += g_pd[i][1]; a2 += g_pd[i][2]; a3 += g_pd[i][3];
        mx = fmaxf(mx, g_pmx[i]);
        mn = fminf(mn, g_pmn[i]);
    }
    sd[t][0] = a0; sd[t][1] = a1; sd[t][2] = a2; sd[t][3] = a3;
    smx[t] = mx; smn[t] = mn;
    __syncthreads();

    for (int off = 128; off > 0; off >>= 1) {
        if (t < off) {
            sd[t][0] += sd[t + off][0];
            sd[t][1] += sd[t + off][1];
            sd[t][2] += sd[t + off][2];
            sd[t][3] += sd[t + off][3];
            smx[t] = fmaxf(smx[t], smx[t + off]);
            smn[t] = fminf(smn[t], smn[t + off]);
        }
        __syncthreads();
    }

    if (t == 0) {
        double maxe = (double)smx[0];   // max S^2
        double mine = (double)smn[0];   // min S^2
        const double NB = (double)BATCH * 25.0;
        double loss = (sd[0][2] / (double)BATCH) * 1e-5              // INV * mean fro
                    + (sd[0][0] / NB - 2.0 * (sd[0][1] / NB) + 1.0)  // DEV * mean (S-1)^2
                    + 0.5 * (log(maxe) - log(mine)) * 0.01           // COND
                    + 1e-6 * sd[0][3];                               // L1 * sum|outp|
        out[0] = (float)loss;
    }
}

extern "C" void kernel_launch(void* const* d_in, const int* in_sizes, int n_in,
                              void* d_out, int out_size) {
    const float* inp  = (const float*)d_in[0];
    const float* outp = (const float*)d_in[1];
    float* out = (float*)d_out;
    (void)in_sizes; (void)n_in; (void)out_size;

    cond_main_kernel<<<NBLOCKS, THREADS>>>(inp, outp);
    cond_final_kernel<<<1, 256>>>(out);
}

// round 4
// speedup vs baseline: 1.5567x; 1.5567x over previous
#include <cuda_runtime.h>
#include <math.h>

#define BATCH  32768
#define NWARPS 8
#define THREADS (NWARPS * 32)
#define NBLOCKS (BATCH / NWARPS)
#define NSWEEP 5

__device__ double g_pd[NBLOCKS][4];   // sum_eig, sum_s, sum_fro, sum_absO
__device__ float  g_pmx[NBLOCKS];
__device__ float  g_pmn[NBLOCKS];

__global__ __launch_bounds__(THREADS)
void cond_main_kernel(const float* __restrict__ inp, const float* __restrict__ outp) {
    __shared__ float  Osh[NWARPS][625];
    __shared__ double redd[NWARPS][4];
    __shared__ float  redmx[NWARPS];
    __shared__ float  redmn[NWARPS];

    const int w    = threadIdx.x >> 5;
    const int lane = threadIdx.x & 31;
    const int b    = blockIdx.x * NWARPS + w;

    const float* O = outp + (size_t)b * 625;
    const float* I = inp  + (size_t)b * 625;
    float* Os = Osh[w];

    const bool act25 = (lane < 25);

    // Load O into smem (coalesced), accumulate sum|O|
    float absO = 0.f;
    for (int idx = lane; idx < 625; idx += 32) {
        float vv = O[idx];
        absO += fabsf(vv);
        Os[idx] = vv;
    }
    // Column `lane` of I into registers
    float Icol[25];
    #pragma unroll
    for (int k = 0; k < 25; k++)
        Icol[k] = act25 ? I[k * 25 + lane] : 0.f;
    __syncwarp();

    // v = column `lane` of C = O @ I ; frosq partial; alpha = ||v||^2
    float v[25];
    float frosq = 0.f;
    float alpha = 0.f;
    #pragma unroll
    for (int i = 0; i < 25; i++) {
        float acc = 0.f;
        #pragma unroll
        for (int k = 0; k < 25; k++)
            acc = fmaf(Os[i * 25 + k], Icol[k], acc);
        v[i] = acc;
        alpha = fmaf(acc, acc, alpha);
        float d = acc - ((i == lane) ? 1.f : 0.f);
        if (act25) frosq += d * d;
    }

    // One-sided (Hestenes) Jacobi, tangent-form updates with deferred scale f.
    // col = f * v;  alpha maintained incrementally (true ||col||^2).
    float f = 1.f;
    for (int sweep = 0; sweep < NSWEEP; sweep++) {
        for (int r = 0; r < 25; r++) {
            int partner = 2 * r - lane;
            partner %= 25;
            if (partner < 0) partner += 25;
            const bool active = act25 && (partner != lane);

            float o[25];
            float vdot = 0.f;
            #pragma unroll
            for (int i = 0; i < 25; i++) {
                o[i] = __shfl_sync(0xffffffffu, v[i], partner);
                vdot = fmaf(v[i], o[i], vdot);
            }
            float alpha_o = __shfl_sync(0xffffffffu, alpha, partner);
            float f_o     = __shfl_sync(0xffffffffu, f, partner);

            float gam = f * f_o * vdot;          // true <col, col_o>

            float c = 1.f, t = 0.f;
            if (active && fabsf(gam) > 1e-28f) {
                float zeta = __fdividef(alpha_o - alpha, 2.f * gam);
                t = __fdividef(1.f, fabsf(zeta) + sqrtf(fmaf(zeta, zeta, 1.f)));
                t = copysignf(t, zeta);
                c = rsqrtf(fmaf(t, t, 1.f));
            }
            float s  = t * c;
            // v <- v - (t * f_o / f) * o   (col' = c*(col - (s/c)*col_o), f' = c*f)
            float coef = -t * __fdividef(f_o, f);
            #pragma unroll
            for (int i = 0; i < 25; i++)
                v[i] = fmaf(coef, o[i], v[i]);
            // alpha' = c^2*alpha + s^2*alpha_o - 2*c*s*gam   (exact identity)
            float cc = c * c, ss = s * s;
            alpha = fmaf(cc, alpha, fmaf(ss, alpha_o, -2.f * c * s * gam));
            f *= c;
        }
        // Renormalize scale into v once per sweep (keeps f away from underflow)
        #pragma unroll
        for (int i = 0; i < 25; i++) v[i] *= f;
        f = 1.f;
    }

    // Final singular values: recompute exactly, alpha = ||v||^2 (f == 1 here)
    float aex = 0.f;
    #pragma unroll
    for (int i = 0; i < 25; i++) aex = fmaf(v[i], v[i], aex);

    float ac   = fmaxf(aex, 1e-12f);
    float Sv   = sqrtf(aex);
    float suma = act25 ? aex : 0.f;
    float sums = act25 ? Sv : 0.f;
    float mxa  = act25 ? ac : 0.f;
    float mna  = act25 ? ac : 3.0e38f;

    #pragma unroll
    for (int off = 16; off > 0; off >>= 1) {
        suma  += __shfl_xor_sync(0xffffffffu, suma, off);
        sums  += __shfl_xor_sync(0xffffffffu, sums, off);
        frosq += __shfl_xor_sync(0xffffffffu, frosq, off);
        absO  += __shfl_xor_sync(0xffffffffu, absO, off);
        mxa = fmaxf(mxa, __shfl_xor_sync(0xffffffffu, mxa, off));
        mna = fminf(mna, __shfl_xor_sync(0xffffffffu, mna, off));
    }
    if (lane == 0) {
        redd[w][0] = (double)suma;
        redd[w][1] = (double)sums;
        redd[w][2] = (double)sqrtf(frosq);
        redd[w][3] = (double)absO;
        redmx[w] = mxa;
        redmn[w] = mna;
    }
    __syncthreads();

    if (threadIdx.x == 0) {
        double a0 = 0.0, a1 = 0.0, s2 = 0.0, a3 = 0.0;
        float mx = 0.f, mn = 3.0e38f;
        #pragma unroll
        for (int i = 0; i < NWARPS; i++) {
            a0 += redd[i][0]; a1 += redd[i][1]; s2 += redd[i][2]; a3 += redd[i][3];
            mx = fmaxf(mx, redmx[i]);
            mn = fminf(mn, redmn[i]);
        }
        g_pd[blockIdx.x][0] = a0;
        g_pd[blockIdx.x][1] = a1;
        g_pd[blockIdx.x][2] = s2;
        g_pd[blockIdx.x][3] = a3;
        g_pmx[blockIdx.x] = mx;
        g_pmn[blockIdx.x] = mn;
    }
}

__global__ __launch_bounds__(256)
void cond_final_kernel(float* __restrict__ out) {
    __shared__ double sd[256][4];
    __shared__ float  smx[256];
    __shared__ float  smn[256];

    const int t = threadIdx.x;
    double a0 = 0.0, a1 = 0.0, a2 = 0.0, a3 = 0.0;
    float mx = 0.f, mn = 3.0e38f;
    for (int i = t; i < NBLOCKS; i += 256) {
        a0 += g_pd[i][0]; a1 += g_pd[i][1]; a2 += g_pd[i][2]; a3 += g_pd[i][3];
        mx = fmaxf(mx, g_pmx[i]);
        mn = fminf(mn, g_pmn[i]);
    }
    sd[t][0] = a0; sd[t][1] = a1; sd[t][2] = a2; sd[t][3] = a3;
    smx[t] = mx; smn[t] = mn;
    __syncthreads();

    for (int off = 128; off > 0; off >>= 1) {
        if (t < off) {
            sd[t][0] += sd[t + off][0];
            sd[t][1] += sd[t + off][1];
            sd[t][2] += sd[t + off][2];
            sd[t][3] += sd[t + off][3];
            smx[t] = fmaxf(smx[t], smx[t + off]);
            smn[t] = fminf(smn[t], smn[t + off]);
        }
        __syncthreads();
    }

    if (t == 0) {
        double maxe = (double)smx[0];   // max S^2
        double mine = (double)smn[0];   // min S^2
        const double NB = (double)BATCH * 25.0;
        double loss = (sd[0][2] / (double)BATCH) * 1e-5              // INV * mean fro
                    + (sd[0][0] / NB - 2.0 * (sd[0][1] / NB) + 1.0)  // DEV * mean (S-1)^2
                    + 0.5 * (log(maxe) - log(mine)) * 0.01           // COND
                    + 1e-6 * sd[0][3];                               // L1 * sum|outp|
        out[0] = (float)loss;
    }
}

extern "C" void kernel_launch(void* const* d_in, const int* in_sizes, int n_in,
                              void* d_out, int out_size) {
    const float* inp  = (const float*)d_in[0];
    const float* outp = (const float*)d_in[1];
    float* out = (float*)d_out;
    (void)in_sizes; (void)n_in; (void)out_size;

    cond_main_kernel<<<NBLOCKS, THREADS>>>(inp, outp);
    cond_final_kernel<<<1, 256>>>(out);
}

// round 5
// speedup vs baseline: 1.5620x; 1.0034x over previous
#include <cuda_runtime.h>
#include <math.h>

#define BATCH  32768
#define NWARPS 4
#define THREADS (NWARPS * 32)
#define NBLOCKS (BATCH / NWARPS)
#define MAXSWEEP 5

__device__ double g_pd[NBLOCKS][4];   // sum_eig, sum_s, sum_fro, sum_absO
__device__ float  g_pmx[NBLOCKS];
__device__ float  g_pmn[NBLOCKS];

__global__ __launch_bounds__(THREADS)
void cond_main_kernel(const float* __restrict__ inp, const float* __restrict__ outp) {
    __shared__ float  Osh[NWARPS][625];
    __shared__ double redd[NWARPS][4];
    __shared__ float  redmx[NWARPS];
    __shared__ float  redmn[NWARPS];

    const int w    = threadIdx.x >> 5;
    const int lane = threadIdx.x & 31;
    const int b    = blockIdx.x * NWARPS + w;

    const float* O = outp + (size_t)b * 625;
    const float* I = inp  + (size_t)b * 625;
    float* Os = Osh[w];

    const bool act25 = (lane < 25);

    // Load O into smem (coalesced), accumulate sum|O|
    float absO = 0.f;
    for (int idx = lane; idx < 625; idx += 32) {
        float vv = O[idx];
        absO += fabsf(vv);
        Os[idx] = vv;
    }
    // Column `lane` of I into registers
    float Icol[25];
    #pragma unroll
    for (int k = 0; k < 25; k++)
        Icol[k] = act25 ? I[k * 25 + lane] : 0.f;
    __syncwarp();

    // v = column `lane` of C = O @ I ; frosq partial; alpha = ||v||^2
    float v[25];
    float frosq = 0.f;
    float alpha = 0.f;
    #pragma unroll
    for (int i = 0; i < 25; i++) {
        float acc = 0.f;
        #pragma unroll
        for (int k = 0; k < 25; k++)
            acc = fmaf(Os[i * 25 + k], Icol[k], acc);
        v[i] = acc;
        alpha = fmaf(acc, acc, alpha);
        float d = acc - ((i == lane) ? 1.f : 0.f);
        if (act25) frosq += d * d;
    }

    // One-sided (Hestenes) Jacobi, tangent-form with deferred scale f.
    // Round r: lane pairs with (2r - lane) mod 25; partner kept incrementally.
    float f = 1.f;
    int partner0 = (25 - lane) % 25;   // partner at r=0 (for lane<25); junk otherwise ok
    if (lane >= 25) partner0 = 0;
    for (int sweep = 0; sweep < MAXSWEEP; sweep++) {
        int partner = partner0;
        bool conv = true;
        for (int r = 0; r < 25; r++) {
            const bool active = act25 && (partner != lane);

            float o[25];
            float d0 = 0.f, d1 = 0.f;   // split dot chains
            #pragma unroll
            for (int i = 0; i < 12; i++) {
                o[i] = __shfl_sync(0xffffffffu, v[i], partner);
                d0 = fmaf(v[i], o[i], d0);
            }
            #pragma unroll
            for (int i = 12; i < 25; i++) {
                o[i] = __shfl_sync(0xffffffffu, v[i], partner);
                d1 = fmaf(v[i], o[i], d1);
            }
            float vdot = d0 + d1;
            float alpha_o = __shfl_sync(0xffffffffu, alpha, partner);
            float f_o     = __shfl_sync(0xffffffffu, f, partner);

            float gam = f * f_o * vdot;          // true <col, col_o>

            float c = 1.f, t = 0.f;
            if (active && fabsf(gam) > 1e-28f) {
                float zeta = __fdividef(alpha_o - alpha, 2.f * gam);
                t = __fdividef(1.f, fabsf(zeta) + sqrtf(fmaf(zeta, zeta, 1.f)));
                t = copysignf(t, zeta);
                c = rsqrtf(fmaf(t, t, 1.f));
            }
            if (active)
                conv = conv && (gam * gam <= 9e-6f * alpha * alpha_o);

            float s  = t * c;
            float coef = -t * __fdividef(f_o, f);
            #pragma unroll
            for (int i = 0; i < 25; i++)
                v[i] = fmaf(coef, o[i], v[i]);
            // alpha' = c^2*alpha + s^2*alpha_o - 2*c*s*gam (exact identity)
            float cc = c * c, ss = s * s;
            alpha = fmaf(cc, alpha, fmaf(ss, alpha_o, -2.f * c * s * gam));
            f *= c;

            partner += 2;
            if (partner >= 25) partner -= 25;
        }
        // Fold scale into v at sweep end (f stays away from underflow)
        #pragma unroll
        for (int i = 0; i < 25; i++) v[i] *= f;
        f = 1.f;
        if (__all_sync(0xffffffffu, conv)) break;
    }

    // Final singular values: exact recompute, 4 chains
    float a0 = 0.f, a1 = 0.f, a2 = 0.f, a3 = 0.f;
    #pragma unroll
    for (int i = 0; i < 24; i += 4) {
        a0 = fmaf(v[i],     v[i],     a0);
        a1 = fmaf(v[i + 1], v[i + 1], a1);
        a2 = fmaf(v[i + 2], v[i + 2], a2);
        a3 = fmaf(v[i + 3], v[i + 3], a3);
    }
    a0 = fmaf(v[24], v[24], a0);
    float aex = (a0 + a1) + (a2 + a3);

    float ac   = fmaxf(aex, 1e-12f);
    float Sv   = sqrtf(aex);
    float suma = act25 ? aex : 0.f;
    float sums = act25 ? Sv : 0.f;
    float mxa  = act25 ? ac : 0.f;
    float mna  = act25 ? ac : 3.0e38f;

    #pragma unroll
    for (int off = 16; off > 0; off >>= 1) {
        suma  += __shfl_xor_sync(0xffffffffu, suma, off);
        sums  += __shfl_xor_sync(0xffffffffu, sums, off);
        frosq += __shfl_xor_sync(0xffffffffu, frosq, off);
        absO  += __shfl_xor_sync(0xffffffffu, absO, off);
        mxa = fmaxf(mxa, __shfl_xor_sync(0xffffffffu, mxa, off));
        mna = fminf(mna, __shfl_xor_sync(0xffffffffu, mna, off));
    }
    if (lane == 0) {
        redd[w][0] = (double)suma;
        redd[w][1] = (double)sums;
        redd[w][2] = (double)sqrtf(frosq);
        redd[w][3] = (double)absO;
        redmx[w] = mxa;
        redmn[w] = mna;
    }
    __syncthreads();

    if (threadIdx.x == 0) {
        double s0 = 0.0, s1 = 0.0, s2 = 0.0, s3 = 0.0;
        float mx = 0.f, mn = 3.0e38f;
        #pragma unroll
        for (int i = 0; i < NWARPS; i++) {
            s0 += redd[i][0]; s1 += redd[i][1]; s2 += redd[i][2]; s3 += redd[i][3];
            mx = fmaxf(mx, redmx[i]);
            mn = fminf(mn, redmn[i]);
        }
        g_pd[blockIdx.x][0] = s0;
        g_pd[blockIdx.x][1] = s1;
        g_pd[blockIdx.x][2] = s2;
        g_pd[blockIdx.x][3] = s3;
        g_pmx[blockIdx.x] = mx;
        g_pmn[blockIdx.x] = mn;
    }
}

__global__ __launch_bounds__(256)
void cond_final_kernel(float* __restrict__ out) {
    __shared__ double sd[256][4];
    __shared__ float  smx[256];
    __shared__ float  smn[256];

    const int t = threadIdx.x;
    double a0 = 0.0, a1 = 0.0, a2 = 0.0, a3 = 0.0;
    float mx = 0.f, mn = 3.0e38f;
    for (int i = t; i < NBLOCKS; i += 256) {
        a0 += g_pd[i][0]; a1 += g_pd[i][1]; a2 += g_pd[i][2]; a3 += g_pd[i][3];
        mx = fmaxf(mx, g_pmx[i]);
        mn = fminf(mn, g_pmn[i]);
    }
    sd[t][0] = a0; sd[t][1] = a1; sd[t][2] = a2; sd[t][3] = a3;
    smx[t] = mx; smn[t] = mn;
    __syncthreads();

    for (int off = 128; off > 0; off >>= 1) {
        if (t < off) {
            sd[t][0] += sd[t + off][0];
            sd[t][1] += sd[t + off][1];
            sd[t][2] += sd[t + off][2];
            sd[t][3] += sd[t + off][3];
            smx[t] = fmaxf(smx[t], smx[t + off]);
            smn[t] = fminf(smn[t], smn[t + off]);
        }
        __syncthreads();
    }

    if (t == 0) {
        double maxe = (double)smx[0];   // max S^2
        double mine = (double)smn[0];   // min S^2
        const double NB = (double)BATCH * 25.0;
        double loss = (sd[0][2] / (double)BATCH) * 1e-5              // INV * mean fro
                    + (sd[0][0] / NB - 2.0 * (sd[0][1] / NB) + 1.0)  // DEV * mean (S-1)^2
                    + 0.5 * (log(maxe) - log(mine)) * 0.01           // COND
                    + 1e-6 * sd[0][3];                               // L1 * sum|outp|
        out[0] = (float)loss;
    }
}

extern "C" void kernel_launch(void* const* d_in, const int* in_sizes, int n_in,
                              void* d_out, int out_size) {
    const float* inp  = (const float*)d_in[0];
    const float* outp = (const float*)d_in[1];
    float* out = (float*)d_out;
    (void)in_sizes; (void)n_in; (void)out_size;

    cond_main_kernel<<<NBLOCKS, THREADS>>>(inp, outp);
    cond_final_kernel<<<1, 256>>>(out);
}

// round 6
// speedup vs baseline: 1.9574x; 1.2531x over previous
#include <cuda_runtime.h>
#include <math.h>

#define BATCH  32768
#define NWARPS 4
#define THREADS (NWARPS * 32)
#define NBLOCKS (BATCH / NWARPS)
#define NSWEEP 4

__device__ double g_pd[NBLOCKS][4];   // sum_eig, sum_s, sum_fro, sum_absO
__device__ float  g_pmx[NBLOCKS];
__device__ float  g_pmn[NBLOCKS];

__global__ __launch_bounds__(THREADS)
void cond_main_kernel(const float* __restrict__ inp, const float* __restrict__ outp) {
    __shared__ float  Osh[NWARPS][625];
    __shared__ double redd[NWARPS][4];
    __shared__ float  redmx[NWARPS];
    __shared__ float  redmn[NWARPS];

    const int w    = threadIdx.x >> 5;
    const int lane = threadIdx.x & 31;
    const int b    = blockIdx.x * NWARPS + w;

    const float* O = outp + (size_t)b * 625;
    const float* I = inp  + (size_t)b * 625;
    float* Os = Osh[w];

    const bool act25 = (lane < 25);

    // Load O into smem (coalesced), accumulate sum|O|
    float absO = 0.f;
    for (int idx = lane; idx < 625; idx += 32) {
        float vv = O[idx];
        absO += fabsf(vv);
        Os[idx] = vv;
    }
    // Column `lane` of I into registers
    float Icol[25];
    #pragma unroll
    for (int k = 0; k < 25; k++)
        Icol[k] = act25 ? I[k * 25 + lane] : 0.f;
    __syncwarp();

    // v = column `lane` of C = O @ I ; frosq partial; alpha = ||v||^2
    float v[25];
    float frosq = 0.f;
    float alpha = 0.f;
    #pragma unroll
    for (int i = 0; i < 25; i++) {
        float acc = 0.f;
        #pragma unroll
        for (int k = 0; k < 25; k++)
            acc = fmaf(Os[i * 25 + k], Icol[k], acc);
        v[i] = acc;
        alpha = fmaf(acc, acc, alpha);
        float d = acc - ((i == lane) ? 1.f : 0.f);
        if (act25) frosq += d * d;
    }

    // One-sided (Hestenes) Jacobi, tangent-form with deferred scale f.
    // Round r: lane pairs with (2r - lane) mod 25; partner kept incrementally.
    float f = 1.f;
    int partner0 = (lane == 0) ? 0 : (25 - lane);
    if (lane >= 25) partner0 = 0;
    for (int sweep = 0; sweep < NSWEEP; sweep++) {
        int partner = partner0;
        for (int r = 0; r < 25; r++) {
            const bool active = act25 && (partner != lane);

            float o[25];
            float d0 = 0.f, d1 = 0.f;   // split dot chains
            #pragma unroll
            for (int i = 0; i < 12; i++) {
                o[i] = __shfl_sync(0xffffffffu, v[i], partner);
                d0 = fmaf(v[i], o[i], d0);
            }
            #pragma unroll
            for (int i = 12; i < 25; i++) {
                o[i] = __shfl_sync(0xffffffffu, v[i], partner);
                d1 = fmaf(v[i], o[i], d1);
            }
            float vdot = d0 + d1;
            float alpha_o = __shfl_sync(0xffffffffu, alpha, partner);
            float f_o     = __shfl_sync(0xffffffffu, f, partner);

            float gam = f * f_o * vdot;          // true <col, col_o>

            float c = 1.f, t = 0.f;
            if (active && fabsf(gam) > 1e-28f) {
                float zeta = __fdividef(alpha_o - alpha, 2.f * gam);
                t = __fdividef(1.f, fabsf(zeta) + sqrtf(fmaf(zeta, zeta, 1.f)));
                t = copysignf(t, zeta);
                c = rsqrtf(fmaf(t, t, 1.f));
            }

            float s  = t * c;
            float coef = -t * __fdividef(f_o, f);
            #pragma unroll
            for (int i = 0; i < 25; i++)
                v[i] = fmaf(coef, o[i], v[i]);
            // alpha' = c^2*alpha + s^2*alpha_o - 2*c*s*gam (exact identity)
            float cc = c * c, ss = s * s;
            alpha = fmaf(cc, alpha, fmaf(ss, alpha_o, -2.f * c * s * gam));
            f *= c;

            partner += 2;
            if (partner >= 25) partner -= 25;
        }
        // Fold scale into v at sweep end (f stays away from underflow)
        #pragma unroll
        for (int i = 0; i < 25; i++) v[i] *= f;
        f = 1.f;
    }

    // Final singular values: exact recompute, 4 chains
    float a0 = 0.f, a1 = 0.f, a2 = 0.f, a3 = 0.f;
    #pragma unroll
    for (int i = 0; i < 24; i += 4) {
        a0 = fmaf(v[i],     v[i],     a0);
        a1 = fmaf(v[i + 1], v[i + 1], a1);
        a2 = fmaf(v[i + 2], v[i + 2], a2);
        a3 = fmaf(v[i + 3], v[i + 3], a3);
    }
    a0 = fmaf(v[24], v[24], a0);
    float aex = (a0 + a1) + (a2 + a3);

    float ac   = fmaxf(aex, 1e-12f);
    float Sv   = sqrtf(aex);
    float suma = act25 ? aex : 0.f;
    float sums = act25 ? Sv : 0.f;
    float mxa  = act25 ? ac : 0.f;
    float mna  = act25 ? ac : 3.0e38f;

    #pragma unroll
    for (int off = 16; off > 0; off >>= 1) {
        suma  += __shfl_xor_sync(0xffffffffu, suma, off);
        sums  += __shfl_xor_sync(0xffffffffu, sums, off);
        frosq += __shfl_xor_sync(0xffffffffu, frosq, off);
        absO  += __shfl_xor_sync(0xffffffffu, absO, off);
        mxa = fmaxf(mxa, __shfl_xor_sync(0xffffffffu, mxa, off));
        mna = fminf(mna, __shfl_xor_sync(0xffffffffu, mna, off));
    }
    if (lane == 0) {
        redd[w][0] = (double)suma;
        redd[w][1] = (double)sums;
        redd[w][2] = (double)sqrtf(frosq);
        redd[w][3] = (double)absO;
        redmx[w] = mxa;
        redmn[w] = mna;
    }
    __syncthreads();

    if (threadIdx.x == 0) {
        double s0 = 0.0, s1 = 0.0, s2 = 0.0, s3 = 0.0;
        float mx = 0.f, mn = 3.0e38f;
        #pragma unroll
        for (int i = 0; i < NWARPS; i++) {
            s0 += redd[i][0]; s1 += redd[i][1]; s2 += redd[i][2]; s3 += redd[i][3];
            mx = fmaxf(mx, redmx[i]);
            mn = fminf(mn, redmn[i]);
        }
        g_pd[blockIdx.x][0] = s0;
        g_pd[blockIdx.x][1] = s1;
        g_pd[blockIdx.x][2] = s2;
        g_pd[blockIdx.x][3] = s3;
        g_pmx[blockIdx.x] = mx;
        g_pmn[blockIdx.x] = mn;
    }
}

__global__ __launch_bounds__(256)
void cond_final_kernel(float* __restrict__ out) {
    __shared__ double sd[256][4];
    __shared__ float  smx[256];
    __shared__ float  smn[256];

    const int t = threadIdx.x;
    double a0 = 0.0, a1 = 0.0, a2 = 0.0, a3 = 0.0;
    float mx = 0.f, mn = 3.0e38f;
    for (int i = t; i < NBLOCKS; i += 256) {
        a0 += g_pd[i][0]; a1 += g_pd[i][1]; a2 += g_pd[i][2]; a3 += g_pd[i][3];
        mx = fmaxf(mx, g_pmx[i]);
        mn = fminf(mn, g_pmn[i]);
    }
    sd[t][0] = a0; sd[t][1] = a1; sd[t][2] = a2; sd[t][3] = a3;
    smx[t] = mx; smn[t] = mn;
    __syncthreads();

    for (int off = 128; off > 0; off >>= 1) {
        if (t < off) {
            sd[t][0] += sd[t + off][0];
            sd[t][1] += sd[t + off][1];
            sd[t][2] += sd[t + off][2];
            sd[t][3] += sd[t + off][3];
            smx[t] = fmaxf(smx[t], smx[t + off]);
            smn[t] = fminf(smn[t], smn[t + off]);
        }
        __syncthreads();
    }

    if (t == 0) {
        double maxe = (double)smx[0];   // max S^2
        double mine = (double)smn[0];   // min S^2
        const double NB = (double)BATCH * 25.0;
        double loss = (sd[0][2] / (double)BATCH) * 1e-5              // INV * mean fro
                    + (sd[0][0] / NB - 2.0 * (sd[0][1] / NB) + 1.0)  // DEV * mean (S-1)^2
                    + 0.5 * (log(maxe) - log(mine)) * 0.01           // COND
                    + 1e-6 * sd[0][3];                               // L1 * sum|outp|
        out[0] = (float)loss;
    }
}

extern "C" void kernel_launch(void* const* d_in, const int* in_sizes, int n_in,
                              void* d_out, int out_size) {
    const float* inp  = (const float*)d_in[0];
    const float* outp = (const float*)d_in[1];
    float* out = (float*)d_out;
    (void)in_sizes; (void)n_in; (void)out_size;

    cond_main_kernel<<<NBLOCKS, THREADS>>>(inp, outp);
    cond_final_kernel<<<1, 256>>>(out);
}

// round 8
// speedup vs baseline: 2.9598x; 1.5121x over previous
#include <cuda_runtime.h>
#include <cuda_fp16.h>
#include <math.h>

#define BATCH  32768
#define NWARPS 4
#define THREADS (NWARPS * 32)
#define NBLOCKS (BATCH / (NWARPS * 2))   // 4096: 2 matrices per warp
#define NSWEEP 4

__device__ double g_pd[NBLOCKS][4];   // sum_eig, sum_s, sum_fro, sum_absO
__device__ float  g_pmx[NBLOCKS];
__device__ float  g_pmn[NBLOCKS];

static __device__ __forceinline__ unsigned h2u(__half2 h) { return *reinterpret_cast<unsigned*>(&h); }
static __device__ __forceinline__ __half2  u2h(unsigned u) { return *reinterpret_cast<__half2*>(&u); }

__global__ __launch_bounds__(THREADS)
void cond_main_kernel(const float* __restrict__ inp, const float* __restrict__ outp) {
    __shared__ float  Osh[NWARPS][625];
    __shared__ double redd[NWARPS][4];
    __shared__ float  redmx[NWARPS];
    __shared__ float  redmn[NWARPS];

    const int w    = threadIdx.x >> 5;
    const int lane = threadIdx.x & 31;
    const int wg   = blockIdx.x * NWARPS + w;
    const int b0   = 2 * wg;               // this warp handles matrices b0, b0+1
    float* Os = Osh[w];

    const bool act25 = (lane < 25);
    const unsigned FULL = 0xffffffffu;

    const __half2 ONE2  = __float2half2_rn(1.0f);
    const __half2 ZERO2 = __float2half2_rn(0.0f);
    const __half2 MINDEN = __float2half2_rn(1e-3f);

    float absO = 0.f;
    float froA = 0.f, froB = 0.f;
    float alA = 0.f, alB = 0.f;    // fp32 EXACT per-column ||col||^2 (trace source)
    __half2 v2[25];   // lo = matrix A column elem, hi = matrix B (scaled by 1/8)

    // ---- fp32 prologue: per matrix, GEMM C = O@I, fro, alpha; pack to half2 ----
    for (int m = 0; m < 2; m++) {
        const float* O = outp + (size_t)(b0 + m) * 625;
        const float* I = inp  + (size_t)(b0 + m) * 625;
        __syncwarp();   // previous pass's smem reads done before overwrite
        for (int idx = lane; idx < 625; idx += 32) {
            float vv = O[idx];
            absO += fabsf(vv);
            Os[idx] = vv;
        }
        __syncwarp();

        float Icol[25];
        #pragma unroll
        for (int k = 0; k < 25; k++)
            Icol[k] = act25 ? I[k * 25 + lane] : 0.f;

        float fro = 0.f, al = 0.f;
        float vv[25];
        #pragma unroll
        for (int i = 0; i < 25; i++) {
            float acc = 0.f;
            #pragma unroll
            for (int k = 0; k < 25; k++)
                acc = fmaf(Os[i * 25 + k], Icol[k], acc);
            vv[i] = acc;
            al = fmaf(acc, acc, al);
            float d = acc - ((i == lane) ? 1.f : 0.f);
            if (act25) fro += d * d;
        }
        if (m == 0) {
            froA = fro; alA = al;
            #pragma unroll
            for (int i = 0; i < 25; i++)
                v2[i] = __halves2half2(__float2half_rn(vv[i] * 0.125f), __float2half_rn(0.f));
        } else {
            froB = fro; alB = al;
            #pragma unroll
            for (int i = 0; i < 25; i++)
                v2[i] = __halves2half2(__low2half(v2[i]), __float2half_rn(vv[i] * 0.125f));
        }
    }

    // alpha in scaled units (1/64), packed (A,B)
    __half2 a2 = __floats2half2_rn(alA * (1.f / 64.f), alB * (1.f / 64.f));
    __half2 f2 = ONE2;

    int partner0 = (lane == 0) ? 0 : (25 - lane);
    if (lane >= 25) partner0 = 0;

    // ---- packed one-sided Jacobi: both matrices per warp ----
    for (int sweep = 0; sweep < NSWEEP; sweep++) {
        int partner = partner0;
        for (int r = 0; r < 25; r++) {
            const bool active = act25 && (partner != lane);

            __half2 o2[25];
            __half2 d0 = ZERO2, d1 = ZERO2;
            #pragma unroll
            for (int i = 0; i < 12; i++) {
                o2[i] = u2h(__shfl_sync(FULL, h2u(v2[i]), partner));
                d0 = __hfma2(v2[i], o2[i], d0);
            }
            #pragma unroll
            for (int i = 12; i < 25; i++) {
                o2[i] = u2h(__shfl_sync(FULL, h2u(v2[i]), partner));
                d1 = __hfma2(v2[i], o2[i], d1);
            }
            __half2 vdot = __hadd2(d0, d1);
            __half2 a2o = u2h(__shfl_sync(FULL, h2u(a2), partner));
            __half2 f2o = u2h(__shfl_sync(FULL, h2u(f2), partner));

            __half2 g2  = __hmul2(__hmul2(f2, f2o), vdot);   // true <col,col_o>
            __half2 num = __hsub2(a2o, a2);
            __half2 den = __hadd2(g2, g2);
            __half2 aden = __hmax2(__habs2(den), MINDEN);
            __half2 zab = __hmul2(__habs2(num), h2rcp(aden));
            __half2 root = h2sqrt(__hfma2(zab, zab, ONE2));
            __half2 tt = h2rcp(__hadd2(zab, root));
            unsigned sgn = (h2u(num) ^ h2u(den)) & 0x80008000u;
            __half2 t2 = u2h((h2u(tt) & 0x7fff7fffu) | sgn);
            if (!active) t2 = ZERO2;

            __half2 c2 = h2rsqrt(__hfma2(t2, t2, ONE2));
            __half2 coef = __hneg2(__hmul2(t2, __hmul2(f2o, h2rcp(f2))));
            #pragma unroll
            for (int i = 0; i < 25; i++)
                v2[i] = __hfma2(coef, o2[i], v2[i]);

            // alpha' = c^2 a + s^2 a_o - 2 c s g
            __half2 s2h = __hmul2(t2, c2);
            __half2 cc = __hmul2(c2, c2);
            __half2 ss = __hmul2(s2h, s2h);
            __half2 csg = __hmul2(__hmul2(c2, s2h), g2);
            a2 = __hfma2(cc, a2, __hfma2(ss, a2o, __hneg2(__hadd2(csg, csg))));
            f2 = __hmul2(f2, c2);

            // keep f away from small values (prevents vdot overflow)
            if (__low2float(f2) < 0.25f || __high2float(f2) < 0.25f) {
                #pragma unroll
                for (int i = 0; i < 25; i++) v2[i] = __hmul2(v2[i], f2);
                f2 = ONE2;
            }

            partner += 2;
            if (partner >= 25) partner -= 25;
        }
        // sweep end: fold scale; exact (half) alpha refresh kills drift
        #pragma unroll
        for (int i = 0; i < 25; i++) v2[i] = __hmul2(v2[i], f2);
        f2 = ONE2;
        __half2 acc0 = ZERO2, acc1 = ZERO2;
        #pragma unroll
        for (int i = 0; i < 12; i++) acc0 = __hfma2(v2[i], v2[i], acc0);
        #pragma unroll
        for (int i = 12; i < 25; i++) acc1 = __hfma2(v2[i], v2[i], acc1);
        a2 = __hadd2(acc0, acc1);
    }

    // ---- final norms in fp32 (scale back by 64) ----
    float aA = 0.f, aB = 0.f;
    #pragma unroll
    for (int i = 0; i < 25; i++) {
        float lo = __low2float(v2[i]);
        float hi = __high2float(v2[i]);
        aA = fmaf(lo, lo, aA);
        aB = fmaf(hi, hi, aB);
    }
    aA *= 64.f; aB *= 64.f;

    float acA = fmaxf(aA, 1e-12f), acB = fmaxf(aB, 1e-12f);
    // ΣS² from EXACT fp32 prologue alphas (trace invariance) — not from fp16.
    float suma = act25 ? (alA + alB) : 0.f;
    float sums = act25 ? (sqrtf(aA) + sqrtf(aB)) : 0.f;
    float mxa  = act25 ? fmaxf(acA, acB) : 0.f;
    float mna  = act25 ? fminf(acA, acB) : 3.0e38f;

    #pragma unroll
    for (int off = 16; off > 0; off >>= 1) {
        suma += __shfl_xor_sync(FULL, suma, off);
        sums += __shfl_xor_sync(FULL, sums, off);
        froA += __shfl_xor_sync(FULL, froA, off);
        froB += __shfl_xor_sync(FULL, froB, off);
        absO += __shfl_xor_sync(FULL, absO, off);
        mxa = fmaxf(mxa, __shfl_xor_sync(FULL, mxa, off));
        mna = fminf(mna, __shfl_xor_sync(FULL, mna, off));
    }
    if (lane == 0) {
        redd[w][0] = (double)suma;
        redd[w][1] = (double)sums;
        redd[w][2] = (double)(sqrtf(froA) + sqrtf(froB));
        redd[w][3] = (double)absO;
        redmx[w] = mxa;
        redmn[w] = mna;
    }
    __syncthreads();

    if (threadIdx.x == 0) {
        double s0 = 0.0, s1 = 0.0, s2 = 0.0, s3 = 0.0;
        float mx = 0.f, mn = 3.0e38f;
        #pragma unroll
        for (int i = 0; i < NWARPS; i++) {
            s0 += redd[i][0]; s1 += redd[i][1]; s2 += redd[i][2]; s3 += redd[i][3];
            mx = fmaxf(mx, redmx[i]);
            mn = fminf(mn, redmn[i]);
        }
        g_pd[blockIdx.x][0] = s0;
        g_pd[blockIdx.x][1] = s1;
        g_pd[blockIdx.x][2] = s2;
        g_pd[blockIdx.x][3] = s3;
        g_pmx[blockIdx.x] = mx;
        g_pmn[blockIdx.x] = mn;
    }
}

__global__ __launch_bounds__(256)
void cond_final_kernel(float* __restrict__ out) {
    __shared__ double sd[256][4];
    __shared__ float  smx[256];
    __shared__ float  smn[256];

    const int t = threadIdx.x;
    double a0 = 0.0, a1 = 0.0, a2 = 0.0, a3 = 0.0;
    float mx = 0.f, mn = 3.0e38f;
    for (int i = t; i < NBLOCKS; i += 256) {
        a0 += g_pd[i][0]; a1 += g_pd[i][1]; a2 += g_pd[i][2]; a3 += g_pd[i][3];
        mx = fmaxf(mx, g_pmx[i]);
        mn = fminf(mn, g_pmn[i]);
    }
    sd[t][0] = a0; sd[t][1] = a1; sd[t][2] = a2; sd[t][3] = a3;
    smx[t] = mx; smn[t] = mn;
    __syncthreads();

    for (int off = 128; off > 0; off >>= 1) {
        if (t < off) {
            sd[t][0] += sd[t + off][0];
            sd[t][1] += sd[t + off][1];
            sd[t][2] += sd[t + off][2];
            sd[t][3] += sd[t + off][3];
            smx[t] = fmaxf(smx[t], smx[t + off]);
            smn[t] = fminf(smn[t], smn[t + off]);
        }
        __syncthreads();
    }

    if (t == 0) {
        double maxe = (double)smx[0];   // max S^2
        double mine = (double)smn[0];   // min S^2
        const double NB = (double)BATCH * 25.0;
        double loss = (sd[0][2] / (double)BATCH) * 1e-5              // INV * mean fro
                    + (sd[0][0] / NB - 2.0 * (sd[0][1] / NB) + 1.0)  // DEV * mean (S-1)^2
                    + 0.5 * (log(maxe) - log(mine)) * 0.01           // COND
                    + 1e-6 * sd[0][3];                               // L1 * sum|outp|
        out[0] = (float)loss;
    }
}

extern "C" void kernel_launch(void* const* d_in, const int* in_sizes, int n_in,
                              void* d_out, int out_size) {
    const float* inp  = (const float*)d_in[0];
    const float* outp = (const float*)d_in[1];
    float* out = (float*)d_out;
    (void)in_sizes; (void)n_in; (void)out_size;

    cond_main_kernel<<<NBLOCKS, THREADS>>>(inp, outp);
    cond_final_kernel<<<1, 256>>>(out);
}

// round 9
// speedup vs baseline: 3.6264x; 1.2252x over previous
#include <cuda_runtime.h>
#include <cuda_fp16.h>
#include <math.h>

#define BATCH  32768
#define NWARPS 4
#define THREADS (NWARPS * 32)
#define NBLOCKS (BATCH / (NWARPS * 2))   // 4096: 2 matrices per warp
#define NSWEEP 3
#define OSTR 28                          // padded row stride (floats), 16B-aligned rows

__device__ double g_pd[NBLOCKS][4];   // sum_eig, sum_s, sum_fro, sum_absO
__device__ float  g_pmx[NBLOCKS];
__device__ float  g_pmn[NBLOCKS];

static __device__ __forceinline__ unsigned h2u(__half2 h) { return *reinterpret_cast<unsigned*>(&h); }
static __device__ __forceinline__ __half2  u2h(unsigned u) { return *reinterpret_cast<__half2*>(&u); }

__global__ __launch_bounds__(THREADS)
void cond_main_kernel(const float* __restrict__ inp, const float* __restrict__ outp) {
    __shared__ __align__(16) float Osh[NWARPS][25 * OSTR + 4];
    __shared__ double redd[NWARPS][4];
    __shared__ float  redmx[NWARPS];
    __shared__ float  redmn[NWARPS];

    const int w    = threadIdx.x >> 5;
    const int lane = threadIdx.x & 31;
    const int wg   = blockIdx.x * NWARPS + w;
    const int b0   = 2 * wg;               // this warp handles matrices b0, b0+1
    float* Os = Osh[w];

    const bool act25 = (lane < 25);
    const unsigned FULL = 0xffffffffu;

    const __half2 ONE2  = __float2half2_rn(1.0f);
    const __half2 ZERO2 = __float2half2_rn(0.0f);
    const __half2 MINDEN = __float2half2_rn(1e-3f);

    float absO = 0.f;
    float froA = 0.f, froB = 0.f;
    float alA = 0.f, alB = 0.f;    // fp32 EXACT per-column ||col||^2 (trace source)
    __half2 v2[25];   // lo = matrix A column elem, hi = matrix B (scaled by 1/8)

    // ---- fp32 prologue: per matrix, GEMM C = O@I, fro, alpha; pack to half2 ----
    for (int m = 0; m < 2; m++) {
        const float* O = outp + (size_t)(b0 + m) * 625;
        const float* I = inp  + (size_t)(b0 + m) * 625;
        __syncwarp();   // previous pass's smem reads done before overwrite
        for (int idx = lane; idx < 625; idx += 32) {
            float vv = O[idx];
            absO += fabsf(vv);
            int i = idx / 25, j = idx - i * 25;
            Os[i * OSTR + j] = vv;
        }
        __syncwarp();

        float Icol[25];
        #pragma unroll
        for (int k = 0; k < 25; k++)
            Icol[k] = act25 ? I[k * 25 + lane] : 0.f;

        float fro = 0.f, al = 0.f;
        float vv[25];
        #pragma unroll
        for (int i = 0; i < 25; i++) {
            const float4* row4 = reinterpret_cast<const float4*>(Os + i * OSTR);
            float acc = 0.f;
            #pragma unroll
            for (int q = 0; q < 6; q++) {
                float4 p = row4[q];
                acc = fmaf(p.x, Icol[4 * q + 0], acc);
                acc = fmaf(p.y, Icol[4 * q + 1], acc);
                acc = fmaf(p.z, Icol[4 * q + 2], acc);
                acc = fmaf(p.w, Icol[4 * q + 3], acc);
            }
            acc = fmaf(Os[i * OSTR + 24], Icol[24], acc);
            vv[i] = acc;
            al = fmaf(acc, acc, al);
            float d = acc - ((i == lane) ? 1.f : 0.f);
            if (act25) fro += d * d;
        }
        if (m == 0) {
            froA = fro; alA = al;
            #pragma unroll
            for (int i = 0; i < 25; i++)
                v2[i] = __halves2half2(__float2half_rn(vv[i] * 0.125f), __float2half_rn(0.f));
        } else {
            froB = fro; alB = al;
            #pragma unroll
            for (int i = 0; i < 25; i++)
                v2[i] = __halves2half2(__low2half(v2[i]), __float2half_rn(vv[i] * 0.125f));
        }
    }

    // alpha in scaled units (1/64), packed (A,B)
    __half2 a2 = __floats2half2_rn(alA * (1.f / 64.f), alB * (1.f / 64.f));
    __half2 f2 = ONE2;

    int partner0 = (lane == 0) ? 0 : (25 - lane);
    if (lane >= 25) partner0 = 0;

    // ---- packed one-sided Jacobi: both matrices per warp ----
    for (int sweep = 0; sweep < NSWEEP; sweep++) {
        int partner = partner0;
        for (int r = 0; r < 25; r++) {
            const bool active = act25 && (partner != lane);

            __half2 o2[25];
            __half2 d0 = ZERO2, d1 = ZERO2;
            #pragma unroll
            for (int i = 0; i < 12; i++) {
                o2[i] = u2h(__shfl_sync(FULL, h2u(v2[i]), partner));
                d0 = __hfma2(v2[i], o2[i], d0);
            }
            #pragma unroll
            for (int i = 12; i < 25; i++) {
                o2[i] = u2h(__shfl_sync(FULL, h2u(v2[i]), partner));
                d1 = __hfma2(v2[i], o2[i], d1);
            }
            __half2 vdot = __hadd2(d0, d1);
            __half2 a2o = u2h(__shfl_sync(FULL, h2u(a2), partner));
            __half2 f2o = u2h(__shfl_sync(FULL, h2u(f2), partner));

            __half2 g2  = __hmul2(__hmul2(f2, f2o), vdot);   // true <col,col_o>
            __half2 num = __hsub2(a2o, a2);
            __half2 den = __hadd2(g2, g2);
            __half2 aden = __hmax2(__habs2(den), MINDEN);
            __half2 zab = __hmul2(__habs2(num), h2rcp(aden));
            __half2 root = h2sqrt(__hfma2(zab, zab, ONE2));
            __half2 tt = h2rcp(__hadd2(zab, root));
            unsigned sgn = (h2u(num) ^ h2u(den)) & 0x80008000u;
            __half2 t2 = u2h((h2u(tt) & 0x7fff7fffu) | sgn);
            if (!active) t2 = ZERO2;

            __half2 c2 = h2rsqrt(__hfma2(t2, t2, ONE2));
            __half2 coef = __hneg2(__hmul2(t2, __hmul2(f2o, h2rcp(f2))));
            #pragma unroll
            for (int i = 0; i < 25; i++)
                v2[i] = __hfma2(coef, o2[i], v2[i]);

            // alpha' = alpha - t*gamma  (exact for optimal t; refreshed per sweep)
            a2 = __hfma2(__hneg2(t2), g2, a2);
            f2 = __hmul2(f2, c2);

            // keep f away from small values (prevents vdot overflow)
            if (__low2float(f2) < 0.25f || __high2float(f2) < 0.25f) {
                #pragma unroll
                for (int i = 0; i < 25; i++) v2[i] = __hmul2(v2[i], f2);
                f2 = ONE2;
            }

            partner += 2;
            if (partner >= 25) partner -= 25;
        }
        // sweep end: fold scale; exact (half) alpha refresh kills drift
        #pragma unroll
        for (int i = 0; i < 25; i++) v2[i] = __hmul2(v2[i], f2);
        f2 = ONE2;
        if (sweep != NSWEEP - 1) {
            __half2 acc0 = ZERO2, acc1 = ZERO2;
            #pragma unroll
            for (int i = 0; i < 12; i++) acc0 = __hfma2(v2[i], v2[i], acc0);
            #pragma unroll
            for (int i = 12; i < 25; i++) acc1 = __hfma2(v2[i], v2[i], acc1);
            a2 = __hadd2(acc0, acc1);
        }
    }

    // ---- final norms in fp32 (scale back by 64) ----
    float aA = 0.f, aB = 0.f;
    #pragma unroll
    for (int i = 0; i < 25; i++) {
        float lo = __low2float(v2[i]);
        float hi = __high2float(v2[i]);
        aA = fmaf(lo, lo, aA);
        aB = fmaf(hi, hi, aB);
    }
    aA *= 64.f; aB *= 64.f;

    float acA = fmaxf(aA, 1e-12f), acB = fmaxf(aB, 1e-12f);
    // ΣS² from EXACT fp32 prologue alphas (trace invariance) — not from fp16.
    float suma = act25 ? (alA + alB) : 0.f;
    float sums = act25 ? (sqrtf(aA) + sqrtf(aB)) : 0.f;
    float mxa  = act25 ? fmaxf(acA, acB) : 0.f;
    float mna  = act25 ? fminf(acA, acB) : 3.0e38f;

    #pragma unroll
    for (int off = 16; off > 0; off >>= 1) {
        suma += __shfl_xor_sync(FULL, suma, off);
        sums += __shfl_xor_sync(FULL, sums, off);
        froA += __shfl_xor_sync(FULL, froA, off);
        froB += __shfl_xor_sync(FULL, froB, off);
        absO += __shfl_xor_sync(FULL, absO, off);
        mxa = fmaxf(mxa, __shfl_xor_sync(FULL, mxa, off));
        mna = fminf(mna, __shfl_xor_sync(FULL, mna, off));
    }
    if (lane == 0) {
        redd[w][0] = (double)suma;
        redd[w][1] = (double)sums;
        redd[w][2] = (double)(sqrtf(froA) + sqrtf(froB));
        redd[w][3] = (double)absO;
        redmx[w] = mxa;
        redmn[w] = mna;
    }
    __syncthreads();

    if (threadIdx.x == 0) {
        double s0 = 0.0, s1 = 0.0, s2 = 0.0, s3 = 0.0;
        float mx = 0.f, mn = 3.0e38f;
        #pragma unroll
        for (int i = 0; i < NWARPS; i++) {
            s0 += redd[i][0]; s1 += redd[i][1]; s2 += redd[i][2]; s3 += redd[i][3];
            mx = fmaxf(mx, redmx[i]);
            mn = fminf(mn, redmn[i]);
        }
        g_pd[blockIdx.x][0] = s0;
        g_pd[blockIdx.x][1] = s1;
        g_pd[blockIdx.x][2] = s2;
        g_pd[blockIdx.x][3] = s3;
        g_pmx[blockIdx.x] = mx;
        g_pmn[blockIdx.x] = mn;
    }
}

__global__ __launch_bounds__(256)
void cond_final_kernel(float* __restrict__ out) {
    __shared__ double sd[256][4];
    __shared__ float  smx[256];
    __shared__ float  smn[256];

    const int t = threadIdx.x;
    double a0 = 0.0, a1 = 0.0, a2 = 0.0, a3 = 0.0;
    float mx = 0.f, mn = 3.0e38f;
    for (int i = t; i < NBLOCKS; i += 256) {
        a0 += g_pd[i][0]; a1 += g_pd[i][1]; a2 += g_pd[i][2]; a3 += g_pd[i][3];
        mx = fmaxf(mx, g_pmx[i]);
        mn = fminf(mn, g_pmn[i]);
    }
    sd[t][0] = a0; sd[t][1] = a1; sd[t][2] = a2; sd[t][3] = a3;
    smx[t] = mx; smn[t] = mn;
    __syncthreads();

    for (int off = 128; off > 0; off >>= 1) {
        if (t < off) {
            sd[t][0] += sd[t + off][0];
            sd[t][1] += sd[t + off][1];
            sd[t][2] += sd[t + off][2];
            sd[t][3] += sd[t + off][3];
            smx[t] = fmaxf(smx[t], smx[t + off]);
            smn[t] = fminf(smn[t], smn[t + off]);
        }
        __syncthreads();
    }

    if (t == 0) {
        double maxe = (double)smx[0];   // max S^2
        double mine = (double)smn[0];   // min S^2
        const double NB = (double)BATCH * 25.0;
        double loss = (sd[0][2] / (double)BATCH) * 1e-5              // INV * mean fro
                    + (sd[0][0] / NB - 2.0 * (sd[0][1] / NB) + 1.0)  // DEV * mean (S-1)^2
                    + 0.5 * (log(maxe) - log(mine)) * 0.01           // COND
                    + 1e-6 * sd[0][3];                               // L1 * sum|outp|
        out[0] = (float)loss;
    }
}

extern "C" void kernel_launch(void* const* d_in, const int* in_sizes, int n_in,
                              void* d_out, int out_size) {
    const float* inp  = (const float*)d_in[0];
    const float* outp = (const float*)d_in[1];
    float* out = (float*)d_out;
    (void)in_sizes; (void)n_in; (void)out_size;

    cond_main_kernel<<<NBLOCKS, THREADS>>>(inp, outp);
    cond_final_kernel<<<1, 256>>>(out);
}

// round 10
// speedup vs baseline: 4.3522x; 1.2002x over previous
#include <cuda_runtime.h>
#include <cuda_fp16.h>
#include <math.h>

#define BATCH  32768
#define NWARPS 4
#define THREADS (NWARPS * 32)
#define NBLOCKS (BATCH / (NWARPS * 2))   // 4096: 2 matrices per warp
#define NSWEEP 3
#define H2STR 28                         // row stride in half2 units (112B, 16B-aligned)

__device__ double g_pd[NBLOCKS][4];   // sum_eig, sum_s, sum_fro, sum_absO
__device__ float  g_pmx[NBLOCKS];
__device__ float  g_pmn[NBLOCKS];

static __device__ __forceinline__ unsigned h2u(__half2 h) { return *reinterpret_cast<unsigned*>(&h); }
static __device__ __forceinline__ __half2  u2h(unsigned u) { return *reinterpret_cast<__half2*>(&u); }

__global__ __launch_bounds__(THREADS)
void cond_main_kernel(const float* __restrict__ inp, const float* __restrict__ outp) {
    __shared__ __align__(16) __half2 Osh[NWARPS][25 * H2STR + 8];
    __shared__ double redd[NWARPS][4];
    __shared__ float  redmx[NWARPS];
    __shared__ float  redmn[NWARPS];

    const int w    = threadIdx.x >> 5;
    const int lane = threadIdx.x & 31;
    const int wg   = blockIdx.x * NWARPS + w;
    const int b0   = 2 * wg;               // this warp handles matrices b0, b0+1
    __half2* Os2 = Osh[w];

    const bool act25 = (lane < 25);
    const unsigned FULL = 0xffffffffu;

    const __half2 ONE2   = __float2half2_rn(1.0f);
    const __half2 ZERO2  = __float2half2_rn(0.0f);
    const __half2 MINDEN = __float2half2_rn(1e-3f);
    const __half2 EIGHTH = __float2half2_rn(0.125f);

    float absO = 0.f;
    float froA = 0.f, froB = 0.f;
    float alA = 0.f, alB = 0.f;    // fp32 per-column ||col||^2 (trace source)
    __half2 v2[25];                // lo = matrix A column elem, hi = matrix B (x 1/8)

    // ---- prologue: load both O matrices packed, packed GEMM C = O@I ----
    {
        const float* OA = outp + (size_t)b0 * 625;
        const float* OB = OA + 625;
        const float* IA = inp + (size_t)b0 * 625;
        const float* IB = IA + 625;

        for (int idx = lane; idx < 625; idx += 32) {
            float a = OA[idx];
            float bv = OB[idx];
            absO += fabsf(a) + fabsf(bv);
            int i = idx / 25, j = idx - i * 25;
            Os2[i * H2STR + j] = __floats2half2_rn(a, bv);
        }
        __half2 Icol2[25];
        #pragma unroll
        for (int k = 0; k < 25; k++) {
            float a = act25 ? IA[k * 25 + lane] : 0.f;
            float bv = act25 ? IB[k * 25 + lane] : 0.f;
            Icol2[k] = __floats2half2_rn(a, bv);
        }
        __syncwarp();

        #pragma unroll
        for (int i = 0; i < 25; i++) {
            const uint4* row4 = reinterpret_cast<const uint4*>(Os2 + i * H2STR);
            __half2 acc = ZERO2;
            #pragma unroll
            for (int q = 0; q < 6; q++) {
                uint4 p = row4[q];
                acc = __hfma2(u2h(p.x), Icol2[4 * q + 0], acc);
                acc = __hfma2(u2h(p.y), Icol2[4 * q + 1], acc);
                acc = __hfma2(u2h(p.z), Icol2[4 * q + 2], acc);
                acc = __hfma2(u2h(p.w), Icol2[4 * q + 3], acc);
            }
            acc = __hfma2(Os2[i * H2STR + 24], Icol2[24], acc);
            // fp32 epilogue: alpha + fro from the (half-rounded) C entries
            float2 cf = __half22float2(acc);
            alA = fmaf(cf.x, cf.x, alA);
            alB = fmaf(cf.y, cf.y, alB);
            float eye = (i == lane) ? 1.f : 0.f;
            float dA = cf.x - eye, dB = cf.y - eye;
            if (act25) { froA = fmaf(dA, dA, froA); froB = fmaf(dB, dB, froB); }
            v2[i] = __hmul2(acc, EIGHTH);
        }
    }

    // alpha in scaled units (1/64), packed (A,B)
    __half2 a2 = __floats2half2_rn(alA * (1.f / 64.f), alB * (1.f / 64.f));
    __half2 f2  = ONE2;   // deferred column scale (product of cosines)
    __half2 rf2 = ONE2;   // 1/f, tracked incrementally (no per-round rcp)

    int partner0 = (lane == 0) ? 0 : (25 - lane);
    if (lane >= 25) partner0 = 0;

    // ---- packed one-sided Jacobi: both matrices per warp ----
    for (int sweep = 0; sweep < NSWEEP; sweep++) {
        int partner = partner0;
        for (int r = 0; r < 25; r++) {
            const bool active = act25 && (partner != lane);

            __half2 o2[25];
            __half2 d0 = ZERO2, d1 = ZERO2;
            #pragma unroll
            for (int i = 0; i < 12; i++) {
                o2[i] = u2h(__shfl_sync(FULL, h2u(v2[i]), partner));
                d0 = __hfma2(v2[i], o2[i], d0);
            }
            #pragma unroll
            for (int i = 12; i < 25; i++) {
                o2[i] = u2h(__shfl_sync(FULL, h2u(v2[i]), partner));
                d1 = __hfma2(v2[i], o2[i], d1);
            }
            __half2 vdot = __hadd2(d0, d1);
            __half2 a2o = u2h(__shfl_sync(FULL, h2u(a2), partner));
            __half2 f2o = u2h(__shfl_sync(FULL, h2u(f2), partner));

            __half2 g2  = __hmul2(__hmul2(f2, f2o), vdot);   // true <col,col_o>
            __half2 num = __hsub2(a2o, a2);
            __half2 den = __hadd2(g2, g2);
            __half2 aden = __hmax2(__habs2(den), MINDEN);
            __half2 zab = __hmul2(__habs2(num), h2rcp(aden));
            __half2 root = h2sqrt(__hfma2(zab, zab, ONE2));
            __half2 tt = h2rcp(__hadd2(zab, root));
            unsigned sgn = (h2u(num) ^ h2u(den)) & 0x80008000u;
            __half2 t2 = u2h((h2u(tt) & 0x7fff7fffu) | sgn);
            if (!active) t2 = ZERO2;

            __half2 q2  = __hfma2(t2, t2, ONE2);   // 1 + t^2
            __half2 rq2 = h2rsqrt(q2);             // = c
            __half2 coef = __hneg2(__hmul2(t2, __hmul2(f2o, rf2)));
            #pragma unroll
            for (int i = 0; i < 25; i++)
                v2[i] = __hfma2(coef, o2[i], v2[i]);

            // alpha' = alpha - t*gamma  (exact for optimal t; refreshed per sweep)
            a2 = __hfma2(__hneg2(t2), g2, a2);
            f2  = __hmul2(f2, rq2);                      // f *= c
            rf2 = __hmul2(rf2, __hmul2(q2, rq2));        // rf *= 1/c = q*rsqrt(q)

            // periodic renorm (f >= 0.0625 guaranteed between checks)
            if ((r & 3) == 3) {
                if (__low2float(f2) < 0.25f || __high2float(f2) < 0.25f) {
                    #pragma unroll
                    for (int i = 0; i < 25; i++) v2[i] = __hmul2(v2[i], f2);
                    f2 = ONE2;
                    rf2 = ONE2;
                }
            }

            partner += 2;
            if (partner >= 25) partner -= 25;
        }
        // sweep end: fold scale; exact (half) alpha refresh kills drift
        #pragma unroll
        for (int i = 0; i < 25; i++) v2[i] = __hmul2(v2[i], f2);
        f2 = ONE2;
        rf2 = ONE2;
        if (sweep != NSWEEP - 1) {
            __half2 acc0 = ZERO2, acc1 = ZERO2;
            #pragma unroll
            for (int i = 0; i < 12; i++) acc0 = __hfma2(v2[i], v2[i], acc0);
            #pragma unroll
            for (int i = 12; i < 25; i++) acc1 = __hfma2(v2[i], v2[i], acc1);
            a2 = __hadd2(acc0, acc1);
        }
    }

    // ---- final norms in fp32 (scale back by 64) ----
    float aA = 0.f, aB = 0.f;
    #pragma unroll
    for (int i = 0; i < 25; i++) {
        float2 cf = __half22float2(v2[i]);
        aA = fmaf(cf.x, cf.x, aA);
        aB = fmaf(cf.y, cf.y, aB);
    }
    aA *= 64.f; aB *= 64.f;

    float acA = fmaxf(aA, 1e-12f), acB = fmaxf(aB, 1e-12f);
    // Sum S^2 from fp32 prologue alphas (trace invariance) — not from fp16 Jacobi.
    float suma = act25 ? (alA + alB) : 0.f;
    float sums = act25 ? (sqrtf(aA) + sqrtf(aB)) : 0.f;
    float mxa  = act25 ? fmaxf(acA, acB) : 0.f;
    float mna  = act25 ? fminf(acA, acB) : 3.0e38f;

    #pragma unroll
    for (int off = 16; off > 0; off >>= 1) {
        suma += __shfl_xor_sync(FULL, suma, off);
        sums += __shfl_xor_sync(FULL, sums, off);
        froA += __shfl_xor_sync(FULL, froA, off);
        froB += __shfl_xor_sync(FULL, froB, off);
        absO += __shfl_xor_sync(FULL, absO, off);
        mxa = fmaxf(mxa, __shfl_xor_sync(FULL, mxa, off));
        mna = fminf(mna, __shfl_xor_sync(FULL, mna, off));
    }
    if (lane == 0) {
        redd[w][0] = (double)suma;
        redd[w][1] = (double)sums;
        redd[w][2] = (double)(sqrtf(froA) + sqrtf(froB));
        redd[w][3] = (double)absO;
        redmx[w] = mxa;
        redmn[w] = mna;
    }
    __syncthreads();

    if (threadIdx.x == 0) {
        double s0 = 0.0, s1 = 0.0, s2 = 0.0, s3 = 0.0;
        float mx = 0.f, mn = 3.0e38f;
        #pragma unroll
        for (int i = 0; i < NWARPS; i++) {
            s0 += redd[i][0]; s1 += redd[i][1]; s2 += redd[i][2]; s3 += redd[i][3];
            mx = fmaxf(mx, redmx[i]);
            mn = fminf(mn, redmn[i]);
        }
        g_pd[blockIdx.x][0] = s0;
        g_pd[blockIdx.x][1] = s1;
        g_pd[blockIdx.x][2] = s2;
        g_pd[blockIdx.x][3] = s3;
        g_pmx[blockIdx.x] = mx;
        g_pmn[blockIdx.x] = mn;
    }
}

__global__ __launch_bounds__(256)
void cond_final_kernel(float* __restrict__ out) {
    __shared__ double sd[256][4];
    __shared__ float  smx[256];
    __shared__ float  smn[256];

    const int t = threadIdx.x;
    double a0 = 0.0, a1 = 0.0, a2 = 0.0, a3 = 0.0;
    float mx = 0.f, mn = 3.0e38f;
    for (int i = t; i < NBLOCKS; i += 256) {
        a0 += g_pd[i][0]; a1 += g_pd[i][1]; a2 += g_pd[i][2]; a3 += g_pd[i][3];
        mx = fmaxf(mx, g_pmx[i]);
        mn = fminf(mn, g_pmn[i]);
    }
    sd[t][0] = a0; sd[t][1] = a1; sd[t][2] = a2; sd[t][3] = a3;
    smx[t] = mx; smn[t] = mn;
    __syncthreads();

    for (int off = 128; off > 0; off >>= 1) {
        if (t < off) {
            sd[t][0] += sd[t + off][0];
            sd[t][1] += sd[t + off][1];
            sd[t][2] += sd[t + off][2];
            sd[t][3] += sd[t + off][3];
            smx[t] = fmaxf(smx[t], smx[t + off]);
            smn[t] = fminf(smn[t], smn[t + off]);
        }
        __syncthreads();
    }

    if (t == 0) {
        double maxe = (double)smx[0];   // max S^2
        double mine = (double)smn[0];   // min S^2
        const double NB = (double)BATCH * 25.0;
        double loss = (sd[0][2] / (double)BATCH) * 1e-5              // INV * mean fro
                    + (sd[0][0] / NB - 2.0 * (sd[0][1] / NB) + 1.0)  // DEV * mean (S-1)^2
                    + 0.5 * (log(maxe) - log(mine)) * 0.01           // COND
                    + 1e-6 * sd[0][3];                               // L1 * sum|outp|
        out[0] = (float)loss;
    }
}

extern "C" void kernel_launch(void* const* d_in, const int* in_sizes, int n_in,
                              void* d_out, int out_size) {
    const float* inp  = (const float*)d_in[0];
    const float* outp = (const float*)d_in[1];
    float* out = (float*)d_out;
    (void)in_sizes; (void)n_in; (void)out_size;

    cond_main_kernel<<<NBLOCKS, THREADS>>>(inp, outp);
    cond_final_kernel<<<1, 256>>>(out);
}

// round 12
// speedup vs baseline: 4.5086x; 1.0359x over previous
#include <cuda_runtime.h>
#include <cuda_fp16.h>
#include <math.h>

#define BATCH  32768
#define NWARPS 4
#define THREADS (NWARPS * 32)
#define NBLOCKS (BATCH / (NWARPS * 2))   // 4096: 2 matrices per warp
#define NSWEEP 3
#define H2STR 28                         // row stride in half2 units (112B, 16B-aligned)

__device__ double g_pd[NBLOCKS][4];   // sum_eig, sum_s, sum_fro, sum_absO
__device__ float  g_pmx[NBLOCKS];
__device__ float  g_pmn[NBLOCKS];

static __device__ __forceinline__ unsigned h2u(__half2 h) { return *reinterpret_cast<unsigned*>(&h); }
static __device__ __forceinline__ __half2  u2h(unsigned u) { return *reinterpret_cast<__half2*>(&u); }

__global__ __launch_bounds__(THREADS)
void cond_main_kernel(const float* __restrict__ inp, const float* __restrict__ outp) {
    __shared__ __align__(16) __half2 Osh[NWARPS][25 * H2STR + 8];
    __shared__ double redd[NWARPS][4];
    __shared__ float  redmx[NWARPS];
    __shared__ float  redmn[NWARPS];

    const int w    = threadIdx.x >> 5;
    const int lane = threadIdx.x & 31;
    const int wg   = blockIdx.x * NWARPS + w;
    const int b0   = 2 * wg;               // this warp handles matrices b0, b0+1
    __half2* Os2 = Osh[w];

    const bool act25 = (lane < 25);
    const unsigned FULL = 0xffffffffu;

    const __half2 ONE2   = __float2half2_rn(1.0f);
    const __half2 ZERO2  = __float2half2_rn(0.0f);
    const __half2 EPSDEN = __float2half2_rn(1e-4f);
    const __half2 EIGHTH = __float2half2_rn(0.125f);

    float absO = 0.f;
    float froA = 0.f, froB = 0.f;
    float alA = 0.f, alB = 0.f;    // fp32 per-column ||col||^2 (trace source)
    __half2 v2[25];                // lo = matrix A column elem, hi = matrix B (x 1/8)

    // ---- prologue: load both O matrices packed, packed GEMM C = O@I ----
    {
        const float* OA = outp + (size_t)b0 * 625;
        const float* OB = OA + 625;
        const float* IA = inp + (size_t)b0 * 625;
        const float* IB = IA + 625;

        for (int idx = lane; idx < 625; idx += 32) {
            float a = OA[idx];
            float bv = OB[idx];
            absO += fabsf(a) + fabsf(bv);
            int i = idx / 25, j = idx - i * 25;
            Os2[i * H2STR + j] = __floats2half2_rn(a, bv);
        }
        __half2 Icol2[25];
        #pragma unroll
        for (int k = 0; k < 25; k++) {
            float a = act25 ? IA[k * 25 + lane] : 0.f;
            float bv = act25 ? IB[k * 25 + lane] : 0.f;
            Icol2[k] = __floats2half2_rn(a, bv);
        }
        __syncwarp();

        #pragma unroll
        for (int i = 0; i < 25; i++) {
            const uint4* row4 = reinterpret_cast<const uint4*>(Os2 + i * H2STR);
            __half2 acc = ZERO2;
            #pragma unroll
            for (int q = 0; q < 6; q++) {
                uint4 p = row4[q];
                acc = __hfma2(u2h(p.x), Icol2[4 * q + 0], acc);
                acc = __hfma2(u2h(p.y), Icol2[4 * q + 1], acc);
                acc = __hfma2(u2h(p.z), Icol2[4 * q + 2], acc);
                acc = __hfma2(u2h(p.w), Icol2[4 * q + 3], acc);
            }
            acc = __hfma2(Os2[i * H2STR + 24], Icol2[24], acc);
            // fp32 epilogue: alpha + fro from the (half-rounded) C entries
            float2 cf = __half22float2(acc);
            alA = fmaf(cf.x, cf.x, alA);
            alB = fmaf(cf.y, cf.y, alB);
            float eye = (i == lane) ? 1.f : 0.f;
            float dA = cf.x - eye, dB = cf.y - eye;
            if (act25) { froA = fmaf(dA, dA, froA); froB = fmaf(dB, dB, froB); }
            v2[i] = __hmul2(acc, EIGHTH);
        }
    }

    // alpha in scaled units (1/64), packed (A,B)
    __half2 a2 = __floats2half2_rn(alA * (1.f / 64.f), alB * (1.f / 64.f));
    __half2 f2  = ONE2;   // deferred column scale (product of cosines)
    __half2 rf2 = ONE2;   // 1/f, tracked incrementally

    int partner0 = (lane == 0) ? 0 : (25 - lane);
    if (lane >= 25) partner0 = 0;

    // ---- packed one-sided Jacobi: both matrices per warp ----
    for (int sweep = 0; sweep < NSWEEP; sweep++) {
        int partner = partner0;
        for (int r = 0; r < 25; r++) {
            const bool active = act25 && (partner != lane);

            __half2 o2[25];
            __half2 d0 = ZERO2, d1 = ZERO2;
            #pragma unroll
            for (int i = 0; i < 12; i++) {
                o2[i] = u2h(__shfl_sync(FULL, h2u(v2[i]), partner));
                d0 = __hfma2(v2[i], o2[i], d0);
            }
            #pragma unroll
            for (int i = 12; i < 25; i++) {
                o2[i] = u2h(__shfl_sync(FULL, h2u(v2[i]), partner));
                d1 = __hfma2(v2[i], o2[i], d1);
            }
            __half2 vdot = __hadd2(d0, d1);
            __half2 a2o = u2h(__shfl_sync(FULL, h2u(a2), partner));
            __half2 f2o = u2h(__shfl_sync(FULL, h2u(f2), partner));

            __half2 g2  = __hmul2(__hmul2(f2, f2o), vdot);   // true <col,col_o>
            __half2 num = __hsub2(a2o, a2);
            __half2 tg  = __hadd2(g2, g2);                   // 2*gamma
            // t = 2g*sign(num) / (|num| + sqrt(num^2 + (2g)^2))
            // homogeneous form: |t| <= 1, no overflow, no z-clamp distortion
            __half2 rad = h2sqrt(__hfma2(num, num, __hmul2(tg, tg)));
            __half2 denom = __hmax2(__hadd2(__habs2(num), rad), EPSDEN);
            __half2 tnum = u2h(h2u(tg) ^ (h2u(num) & 0x80008000u));
            __half2 t2 = __hmul2(tnum, h2rcp(denom));
            if (!active) t2 = ZERO2;

            __half2 q2  = __hfma2(t2, t2, ONE2);   // 1 + t^2
            __half2 rq2 = h2rsqrt(q2);             // = c
            __half2 coef = __hneg2(__hmul2(t2, __hmul2(f2o, rf2)));
            #pragma unroll
            for (int i = 0; i < 25; i++)
                v2[i] = __hfma2(coef, o2[i], v2[i]);

            // alpha' = alpha - t*gamma  (exact for optimal t; refreshed per sweep)
            a2 = __hfma2(__hneg2(t2), g2, a2);
            f2  = __hmul2(f2, rq2);                      // f *= c
            rf2 = __hmul2(rf2, __hmul2(q2, rq2));        // rf *= 1/c = q*rsqrt(q)

            // periodic renorm (f >= 0.0625 guaranteed between checks)
            if ((r & 3) == 3) {
                if (__low2float(f2) < 0.25f || __high2float(f2) < 0.25f) {
                    #pragma unroll
                    for (int i = 0; i < 25; i++) v2[i] = __hmul2(v2[i], f2);
                    f2 = ONE2;
                    rf2 = ONE2;
                }
            }

            partner += 2;
            if (partner >= 25) partner -= 25;
        }
        // sweep end: fold scale; exact (half) alpha refresh kills drift
        #pragma unroll
        for (int i = 0; i < 25; i++) v2[i] = __hmul2(v2[i], f2);
        f2 = ONE2;
        rf2 = ONE2;
        if (sweep != NSWEEP - 1) {
            __half2 acc0 = ZERO2, acc1 = ZERO2;
            #pragma unroll
            for (int i = 0; i < 12; i++) acc0 = __hfma2(v2[i], v2[i], acc0);
            #pragma unroll
            for (int i = 12; i < 25; i++) acc1 = __hfma2(v2[i], v2[i], acc1);
            a2 = __hadd2(acc0, acc1);
        }
    }

    // ---- final norms in fp32 (scale back by 64) ----
    float aA = 0.f, aB = 0.f;
    #pragma unroll
    for (int i = 0; i < 25; i++) {
        float2 cf = __half22float2(v2[i]);
        aA = fmaf(cf.x, cf.x, aA);
        aB = fmaf(cf.y, cf.y, aB);
    }
    aA *= 64.f; aB *= 64.f;

    float acA = fmaxf(aA, 1e-12f), acB = fmaxf(aB, 1e-12f);
    // Sum S^2 from fp32 prologue alphas (trace invariance) — not from fp16 Jacobi.
    float suma = act25 ? (alA + alB) : 0.f;
    float sums = act25 ? (sqrtf(aA) + sqrtf(aB)) : 0.f;
    float mxa  = act25 ? fmaxf(acA, acB) : 0.f;
    float mna  = act25 ? fminf(acA, acB) : 3.0e38f;

    #pragma unroll
    for (int off = 16; off > 0; off >>= 1) {
        suma += __shfl_xor_sync(FULL, suma, off);
        sums += __shfl_xor_sync(FULL, sums, off);
        froA += __shfl_xor_sync(FULL, froA, off);
        froB += __shfl_xor_sync(FULL, froB, off);
        absO += __shfl_xor_sync(FULL, absO, off);
        mxa = fmaxf(mxa, __shfl_xor_sync(FULL, mxa, off));
        mna = fminf(mna, __shfl_xor_sync(FULL, mna, off));
    }
    if (lane == 0) {
        redd[w][0] = (double)suma;
        redd[w][1] = (double)sums;
        redd[w][2] = (double)(sqrtf(froA) + sqrtf(froB));
        redd[w][3] = (double)absO;
        redmx[w] = mxa;
        redmn[w] = mna;
    }
    __syncthreads();

    if (threadIdx.x == 0) {
        double s0 = 0.0, s1 = 0.0, s2 = 0.0, s3 = 0.0;
        float mx = 0.f, mn = 3.0e38f;
        #pragma unroll
        for (int i = 0; i < NWARPS; i++) {
            s0 += redd[i][0]; s1 += redd[i][1]; s2 += redd[i][2]; s3 += redd[i][3];
            mx = fmaxf(mx, redmx[i]);
            mn = fminf(mn, redmn[i]);
        }
        g_pd[blockIdx.x][0] = s0;
        g_pd[blockIdx.x][1] = s1;
        g_pd[blockIdx.x][2] = s2;
        g_pd[blockIdx.x][3] = s3;
        g_pmx[blockIdx.x] = mx;
        g_pmn[blockIdx.x] = mn;
    }
}

#define FTH 1024
__global__ __launch_bounds__(FTH)
void cond_final_kernel(float* __restrict__ out) {
    __shared__ double sd[FTH][4];
    __shared__ float  smx[FTH];
    __shared__ float  smn[FTH];

    const int t = threadIdx.x;
    double a0 = 0.0, a1 = 0.0, a2 = 0.0, a3 = 0.0;
    float mx = 0.f, mn = 3.0e38f;
    for (int i = t; i < NBLOCKS; i += FTH) {
        a0 += g_pd[i][0]; a1 += g_pd[i][1]; a2 += g_pd[i][2]; a3 += g_pd[i][3];
        mx = fmaxf(mx, g_pmx[i]);
        mn = fminf(mn, g_pmn[i]);
    }
    sd[t][0] = a0; sd[t][1] = a1; sd[t][2] = a2; sd[t][3] = a3;
    smx[t] = mx; smn[t] = mn;
    __syncthreads();

    for (int off = FTH / 2; off > 0; off >>= 1) {
        if (t < off) {
            sd[t][0] += sd[t + off][0];
            sd[t][1] += sd[t + off][1];
            sd[t][2] += sd[t + off][2];
            sd[t][3] += sd[t + off][3];
            smx[t] = fmaxf(smx[t], smx[t + off]);
            smn[t] = fminf(smn[t], smn[t + off]);
        }
        __syncthreads();
    }

    if (t == 0) {
        double maxe = (double)smx[0];   // max S^2
        double mine = (double)smn[0];   // min S^2
        const double NB = (double)BATCH * 25.0;
        double loss = (sd[0][2] / (double)BATCH) * 1e-5              // INV * mean fro
                    + (sd[0][0] / NB - 2.0 * (sd[0][1] / NB) + 1.0)  // DEV * mean (S-1)^2
                    + 0.5 * (log(maxe) - log(mine)) * 0.01           // COND
                    + 1e-6 * sd[0][3];                               // L1 * sum|outp|
        out[0] = (float)loss;
    }
}

extern "C" void kernel_launch(void* const* d_in, const int* in_sizes, int n_in,
                              void* d_out, int out_size) {
    const float* inp  = (const float*)d_in[0];
    const float* outp = (const float*)d_in[1];
    float* out = (float*)d_out;
    (void)in_sizes; (void)n_in; (void)out_size;

    cond_main_kernel<<<NBLOCKS, THREADS>>>(inp, outp);
    cond_final_kernel<<<1, FTH>>>(out);
}

// round 13
// speedup vs baseline: 4.5431x; 1.0077x over previous
#include <cuda_runtime.h>
#include <cuda_fp16.h>
#include <math.h>

#define BATCH  32768
#define NWARPS 4
#define THREADS (NWARPS * 32)
#define NBLOCKS (BATCH / (NWARPS * 2))   // 4096: 2 matrices per warp
#define NSWEEP 3
#define H2STR 28                         // row stride in half2 units (112B, 16B-aligned)

__device__ double g_pd[NBLOCKS][4];   // sum_eig, sum_s, sum_fro, sum_absO
__device__ float  g_pmx[NBLOCKS];
__device__ float  g_pmn[NBLOCKS];

static __device__ __forceinline__ unsigned h2u(__half2 h) { return *reinterpret_cast<unsigned*>(&h); }
static __device__ __forceinline__ __half2  u2h(unsigned u) { return *reinterpret_cast<__half2*>(&u); }

__global__ __launch_bounds__(THREADS)
void cond_main_kernel(const float* __restrict__ inp, const float* __restrict__ outp) {
    __shared__ __align__(16) __half2 Osh[NWARPS][25 * H2STR + 8];
    __shared__ double redd[NWARPS][4];
    __shared__ float  redmx[NWARPS];
    __shared__ float  redmn[NWARPS];

    const int w    = threadIdx.x >> 5;
    const int lane = threadIdx.x & 31;
    const int wg   = blockIdx.x * NWARPS + w;
    const int b0   = 2 * wg;               // this warp handles matrices b0, b0+1
    __half2* Os2 = Osh[w];

    const bool act25 = (lane < 25);
    const unsigned FULL = 0xffffffffu;

    const __half2 ONE2   = __float2half2_rn(1.0f);
    const __half2 ZERO2  = __float2half2_rn(0.0f);
    const __half2 EPSDEN = __float2half2_rn(1e-4f);
    const __half2 EIGHTH = __float2half2_rn(0.125f);

    float absO = 0.f;
    float froA = 0.f, froB = 0.f;
    float alA = 0.f, alB = 0.f;    // fp32 per-column ||col||^2 (trace source)
    __half2 v2[25];                // lo = matrix A column elem, hi = matrix B (x 1/8)

    // ---- prologue: load both O matrices packed, packed GEMM C = O@I ----
    {
        const float* OA = outp + (size_t)b0 * 625;
        const float* OB = OA + 625;
        const float* IA = inp + (size_t)b0 * 625;
        const float* IB = IA + 625;

        for (int idx = lane; idx < 625; idx += 32) {
            float a = OA[idx];
            float bv = OB[idx];
            absO += fabsf(a) + fabsf(bv);
            int i = idx / 25, j = idx - i * 25;
            Os2[i * H2STR + j] = __floats2half2_rn(a, bv);
        }
        __half2 Icol2[25];
        #pragma unroll
        for (int k = 0; k < 25; k++) {
            float a = act25 ? IA[k * 25 + lane] : 0.f;
            float bv = act25 ? IB[k * 25 + lane] : 0.f;
            Icol2[k] = __floats2half2_rn(a, bv);
        }
        __syncwarp();

        #pragma unroll
        for (int i = 0; i < 25; i++) {
            const uint4* row4 = reinterpret_cast<const uint4*>(Os2 + i * H2STR);
            __half2 acc = ZERO2;
            #pragma unroll
            for (int q = 0; q < 6; q++) {
                uint4 p = row4[q];
                acc = __hfma2(u2h(p.x), Icol2[4 * q + 0], acc);
                acc = __hfma2(u2h(p.y), Icol2[4 * q + 1], acc);
                acc = __hfma2(u2h(p.z), Icol2[4 * q + 2], acc);
                acc = __hfma2(u2h(p.w), Icol2[4 * q + 3], acc);
            }
            acc = __hfma2(Os2[i * H2STR + 24], Icol2[24], acc);
            float2 cf = __half22float2(acc);
            alA = fmaf(cf.x, cf.x, alA);
            alB = fmaf(cf.y, cf.y, alB);
            float eye = (i == lane) ? 1.f : 0.f;
            float dA = cf.x - eye, dB = cf.y - eye;
            if (act25) { froA = fmaf(dA, dA, froA); froB = fmaf(dB, dB, froB); }
            v2[i] = __hmul2(acc, EIGHTH);
        }
    }

    // alpha in scaled units (1/64), packed (A,B)
    __half2 a2 = __floats2half2_rn(alA * (1.f / 64.f), alB * (1.f / 64.f));
    __half2 f2  = ONE2;   // deferred column scale (product of cosines)
    __half2 rf2 = ONE2;   // 1/f, tracked incrementally

    int partner0 = (lane == 0) ? 0 : (25 - lane);
    if (lane >= 25) partner0 = 0;
    int partner = partner0;

    // One Jacobi round (tangent form, homogeneous-t, packed 2 matrices).
    auto round_body = [&]() {
        const bool active = act25 && (partner != lane);

        __half2 o2[25];
        __half2 d0 = ZERO2, d1 = ZERO2;
        #pragma unroll
        for (int i = 0; i < 12; i++) {
            o2[i] = u2h(__shfl_sync(FULL, h2u(v2[i]), partner));
            d0 = __hfma2(v2[i], o2[i], d0);
        }
        #pragma unroll
        for (int i = 12; i < 25; i++) {
            o2[i] = u2h(__shfl_sync(FULL, h2u(v2[i]), partner));
            d1 = __hfma2(v2[i], o2[i], d1);
        }
        __half2 vdot = __hadd2(d0, d1);
        __half2 a2o = u2h(__shfl_sync(FULL, h2u(a2), partner));
        __half2 f2o = u2h(__shfl_sync(FULL, h2u(f2), partner));

        __half2 g2  = __hmul2(__hmul2(f2, f2o), vdot);   // true <col,col_o>
        __half2 num = __hsub2(a2o, a2);
        __half2 tg  = __hadd2(g2, g2);                   // 2*gamma
        // t = 2g*sign(num) / (|num| + sqrt(num^2 + (2g)^2)); |t| <= 1, no overflow
        __half2 rad = h2sqrt(__hfma2(num, num, __hmul2(tg, tg)));
        __half2 denom = __hmax2(__hadd2(__habs2(num), rad), EPSDEN);
        __half2 tnum = u2h(h2u(tg) ^ (h2u(num) & 0x80008000u));
        __half2 t2 = __hmul2(tnum, h2rcp(denom));
        if (!active) t2 = ZERO2;

        __half2 q2  = __hfma2(t2, t2, ONE2);   // 1 + t^2
        __half2 rq2 = h2rsqrt(q2);             // = c
        __half2 coef = __hneg2(__hmul2(t2, __hmul2(f2o, rf2)));
        #pragma unroll
        for (int i = 0; i < 25; i++)
            v2[i] = __hfma2(coef, o2[i], v2[i]);

        a2 = __hfma2(__hneg2(t2), g2, a2);       // alpha' = alpha - t*gamma
        f2  = __hmul2(f2, rq2);                  // f *= c
        rf2 = __hmul2(rf2, __hmul2(q2, rq2));    // rf *= 1/c

        partner += 2;
        if (partner >= 25) partner -= 25;
    };

    // ---- packed one-sided Jacobi: 25 rounds/sweep = 6 groups of 4 + 1 ----
    for (int sweep = 0; sweep < NSWEEP; sweep++) {
        partner = partner0;
        #pragma unroll 1
        for (int g = 0; g < 6; g++) {
            round_body(); round_body(); round_body(); round_body();
            // renorm once per 4 rounds: f >= 0.0625 guaranteed between checks
            if (__low2float(f2) < 0.25f || __high2float(f2) < 0.25f) {
                #pragma unroll
                for (int i = 0; i < 25; i++) v2[i] = __hmul2(v2[i], f2);
                f2 = ONE2;
                rf2 = ONE2;
            }
        }
        round_body();
        // sweep end: fold scale; (half) alpha refresh kills drift
        #pragma unroll
        for (int i = 0; i < 25; i++) v2[i] = __hmul2(v2[i], f2);
        f2 = ONE2;
        rf2 = ONE2;
        if (sweep != NSWEEP - 1) {
            __half2 acc0 = ZERO2, acc1 = ZERO2;
            #pragma unroll
            for (int i = 0; i < 12; i++) acc0 = __hfma2(v2[i], v2[i], acc0);
            #pragma unroll
            for (int i = 12; i < 25; i++) acc1 = __hfma2(v2[i], v2[i], acc1);
            a2 = __hadd2(acc0, acc1);
        }
    }

    // ---- final norms in fp32 (scale back by 64) ----
    float aA = 0.f, aB = 0.f;
    #pragma unroll
    for (int i = 0; i < 25; i++) {
        float2 cf = __half22float2(v2[i]);
        aA = fmaf(cf.x, cf.x, aA);
        aB = fmaf(cf.y, cf.y, aB);
    }
    aA *= 64.f; aB *= 64.f;

    float acA = fmaxf(aA, 1e-12f), acB = fmaxf(aB, 1e-12f);
    // Sum S^2 from fp32 prologue alphas (trace invariance) — not from fp16 Jacobi.
    float suma = act25 ? (alA + alB) : 0.f;
    float sums = act25 ? (sqrtf(aA) + sqrtf(aB)) : 0.f;
    float mxa  = act25 ? fmaxf(acA, acB) : 0.f;
    float mna  = act25 ? fminf(acA, acB) : 3.0e38f;

    #pragma unroll
    for (int off = 16; off > 0; off >>= 1) {
        suma += __shfl_xor_sync(FULL, suma, off);
        sums += __shfl_xor_sync(FULL, sums, off);
        froA += __shfl_xor_sync(FULL, froA, off);
        froB += __shfl_xor_sync(FULL, froB, off);
        absO += __shfl_xor_sync(FULL, absO, off);
        mxa = fmaxf(mxa, __shfl_xor_sync(FULL, mxa, off));
        mna = fminf(mna, __shfl_xor_sync(FULL, mna, off));
    }
    if (lane == 0) {
        redd[w][0] = (double)suma;
        redd[w][1] = (double)sums;
        redd[w][2] = (double)(sqrtf(froA) + sqrtf(froB));
        redd[w][3] = (double)absO;
        redmx[w] = mxa;
        redmn[w] = mna;
    }
    __syncthreads();

    if (threadIdx.x == 0) {
        double s0 = 0.0, s1 = 0.0, s2 = 0.0, s3 = 0.0;
        float mx = 0.f, mn = 3.0e38f;
        #pragma unroll
        for (int i = 0; i < NWARPS; i++) {
            s0 += redd[i][0]; s1 += redd[i][1]; s2 += redd[i][2]; s3 += redd[i][3];
            mx = fmaxf(mx, redmx[i]);
            mn = fminf(mn, redmn[i]);
        }
        g_pd[blockIdx.x][0] = s0;
        g_pd[blockIdx.x][1] = s1;
        g_pd[blockIdx.x][2] = s2;
        g_pd[blockIdx.x][3] = s3;
        g_pmx[blockIdx.x] = mx;
        g_pmn[blockIdx.x] = mn;
    }
}

#define FTH 1024
__global__ __launch_bounds__(FTH)
void cond_final_kernel(float* __restrict__ out) {
    __shared__ double sd[FTH][4];
    __shared__ float  smx[FTH];
    __shared__ float  smn[FTH];

    const int t = threadIdx.x;
    double a0 = 0.0, a1 = 0.0, a2 = 0.0, a3 = 0.0;
    float mx = 0.f, mn = 3.0e38f;
    for (int i = t; i < NBLOCKS; i += FTH) {
        a0 += g_pd[i][0]; a1 += g_pd[i][1]; a2 += g_pd[i][2]; a3 += g_pd[i][3];
        mx = fmaxf(mx, g_pmx[i]);
        mn = fminf(mn, g_pmn[i]);
    }
    sd[t][0] = a0; sd[t][1] = a1; sd[t][2] = a2; sd[t][3] = a3;
    smx[t] = mx; smn[t] = mn;
    __syncthreads();

    for (int off = FTH / 2; off > 0; off >>= 1) {
        if (t < off) {
            sd[t][0] += sd[t + off][0];
            sd[t][1] += sd[t + off][1];
            sd[t][2] += sd[t + off][2];
            sd[t][3] += sd[t + off][3];
            smx[t] = fmaxf(smx[t], smx[t + off]);
            smn[t] = fminf(smn[t], smn[t + off]);
        }
        __syncthreads();
    }

    if (t == 0) {
        double maxe = (double)smx[0];   // max S^2
        double mine = (double)smn[0];   // min S^2
        const double NB = (double)BATCH * 25.0;
        double loss = (sd[0][2] / (double)BATCH) * 1e-5              // INV * mean fro
                    + (sd[0][0] / NB - 2.0 * (sd[0][1] / NB) + 1.0)  // DEV * mean (S-1)^2
                    + 0.5 * (log(maxe) - log(mine)) * 0.01           // COND
                    + 1e-6 * sd[0][3];                               // L1 * sum|outp|
        out[0] = (float)loss;
    }
}

extern "C" void kernel_launch(void* const* d_in, const int* in_sizes, int n_in,
                              void* d_out, int out_size) {
    const float* inp  = (const float*)d_in[0];
    const float* outp = (const float*)d_in[1];
    float* out = (float*)d_out;
    (void)in_sizes; (void)n_in; (void)out_size;

    cond_main_kernel<<<NBLOCKS, THREADS>>>(inp, outp);
    cond_final_kernel<<<1, FTH>>>(out);
}

// round 14
// speedup vs baseline: 4.5813x; 1.0084x over previous
#include <cuda_runtime.h>
#include <cuda_fp16.h>
#include <math.h>

#define BATCH  32768
#define NWARPS 4
#define THREADS (NWARPS * 32)
#define NBLOCKS (BATCH / (NWARPS * 2))   // 4096: 2 matrices per warp
#define NSWEEP 3
#define H2STR 28                         // row stride in half2 units (112B, 16B-aligned)

__device__ double g_pd[NBLOCKS][4];   // sum_eig, sum_s, sum_fro, sum_absO
__device__ float  g_pmx[NBLOCKS];
__device__ float  g_pmn[NBLOCKS];

static __device__ __forceinline__ unsigned h2u(__half2 h) { return *reinterpret_cast<unsigned*>(&h); }
static __device__ __forceinline__ __half2  u2h(unsigned u) { return *reinterpret_cast<__half2*>(&u); }

__global__ __launch_bounds__(THREADS)
void cond_main_kernel(const float* __restrict__ inp, const float* __restrict__ outp) {
    __shared__ __align__(16) __half2 Osh[NWARPS][25 * H2STR + 8];
    __shared__ double redd[NWARPS][4];
    __shared__ float  redmx[NWARPS];
    __shared__ float  redmn[NWARPS];

    const int w    = threadIdx.x >> 5;
    const int lane = threadIdx.x & 31;
    const int wg   = blockIdx.x * NWARPS + w;
    const int b0   = 2 * wg;               // this warp handles matrices b0, b0+1
    __half2* Os2 = Osh[w];

    const bool act25 = (lane < 25);
    const unsigned FULL = 0xffffffffu;

    const __half2 ONE2   = __float2half2_rn(1.0f);
    const __half2 ZERO2  = __float2half2_rn(0.0f);
    const __half2 EPSDEN = __float2half2_rn(1e-4f);
    const __half2 EIGHTH = __float2half2_rn(0.125f);
    const __half2 BMIN   = __float2half2_rn(0.3398f);   // alpha-max-beta-min hypot coeff

    float absO = 0.f;
    float froA = 0.f, froB = 0.f;
    float alA = 0.f, alB = 0.f;    // fp32 per-column ||col||^2 (trace source)
    __half2 v2[25];                // lo = matrix A column elem, hi = matrix B (x 1/8)

    // ---- prologue: load both O matrices packed, packed GEMM C = O@I ----
    {
        const float* OA = outp + (size_t)b0 * 625;
        const float* OB = OA + 625;
        const float* IA = inp + (size_t)b0 * 625;
        const float* IB = IA + 625;

        for (int idx = lane; idx < 625; idx += 32) {
            float a = OA[idx];
            float bv = OB[idx];
            absO += fabsf(a) + fabsf(bv);
            int i = idx / 25, j = idx - i * 25;
            Os2[i * H2STR + j] = __floats2half2_rn(a, bv);
        }
        __half2 Icol2[25];
        #pragma unroll
        for (int k = 0; k < 25; k++) {
            float a = act25 ? IA[k * 25 + lane] : 0.f;
            float bv = act25 ? IB[k * 25 + lane] : 0.f;
            Icol2[k] = __floats2half2_rn(a, bv);
        }
        __syncwarp();

        #pragma unroll
        for (int i = 0; i < 25; i++) {
            const uint4* row4 = reinterpret_cast<const uint4*>(Os2 + i * H2STR);
            __half2 acc = ZERO2;
            #pragma unroll
            for (int q = 0; q < 6; q++) {
                uint4 p = row4[q];
                acc = __hfma2(u2h(p.x), Icol2[4 * q + 0], acc);
                acc = __hfma2(u2h(p.y), Icol2[4 * q + 1], acc);
                acc = __hfma2(u2h(p.z), Icol2[4 * q + 2], acc);
                acc = __hfma2(u2h(p.w), Icol2[4 * q + 3], acc);
            }
            acc = __hfma2(Os2[i * H2STR + 24], Icol2[24], acc);
            float2 cf = __half22float2(acc);
            alA = fmaf(cf.x, cf.x, alA);
            alB = fmaf(cf.y, cf.y, alB);
            float eye = (i == lane) ? 1.f : 0.f;
            float dA = cf.x - eye, dB = cf.y - eye;
            if (act25) { froA = fmaf(dA, dA, froA); froB = fmaf(dB, dB, froB); }
            v2[i] = __hmul2(acc, EIGHTH);
        }
    }

    // alpha in scaled units (1/64), packed (A,B)
    __half2 a2 = __floats2half2_rn(alA * (1.f / 64.f), alB * (1.f / 64.f));
    __half2 f2  = ONE2;   // deferred column scale (product of cosines)
    __half2 rf2 = ONE2;   // 1/f, tracked incrementally

    int partner0 = (lane == 0) ? 0 : (25 - lane);
    if (lane >= 25) partner0 = 0;
    int partner = partner0;

    // One Jacobi round (tangent form, homogeneous-t, packed 2 matrices).
    auto round_body = [&]() {
        const bool active = act25 && (partner != lane);

        __half2 o2[25];
        __half2 d0 = ZERO2, d1 = ZERO2;
        #pragma unroll
        for (int i = 0; i < 12; i++) {
            o2[i] = u2h(__shfl_sync(FULL, h2u(v2[i]), partner));
            d0 = __hfma2(v2[i], o2[i], d0);
        }
        #pragma unroll
        for (int i = 12; i < 25; i++) {
            o2[i] = u2h(__shfl_sync(FULL, h2u(v2[i]), partner));
            d1 = __hfma2(v2[i], o2[i], d1);
        }
        __half2 vdot = __hadd2(d0, d1);
        __half2 a2o = u2h(__shfl_sync(FULL, h2u(a2), partner));
        __half2 f2o = u2h(__shfl_sync(FULL, h2u(f2), partner));

        __half2 g2  = __hmul2(__hmul2(f2, f2o), vdot);   // true <col,col_o>
        __half2 num = __hsub2(a2o, a2);
        __half2 tg  = __hadd2(g2, g2);                   // 2*gamma
        // t = 2g*sign(num) / (|num| + rad), rad ~ hypot(num, 2g) via amax+bmin
        // (<=5.4% rad error only perturbs the rotation angle; c stays consistent
        //  with t, so norm bookkeeping is exact regardless)
        __half2 ax = __habs2(num);
        __half2 ag = __habs2(tg);
        __half2 mx = __hmax2(ax, ag);
        __half2 mn = __hmin2(ax, ag);
        __half2 rad = __hfma2(mn, BMIN, mx);
        __half2 denom = __hmax2(__hadd2(ax, rad), EPSDEN);
        __half2 tnum = u2h(h2u(tg) ^ (h2u(num) & 0x80008000u));
        __half2 t2 = __hmul2(tnum, h2rcp(denom));
        if (!active) t2 = ZERO2;

        __half2 nt2 = __hneg2(t2);
        __half2 q2  = __hfma2(t2, t2, ONE2);   // 1 + t^2
        __half2 rq2 = h2rsqrt(q2);             // = c
        __half2 coef = __hmul2(nt2, __hmul2(f2o, rf2));
        #pragma unroll
        for (int i = 0; i < 25; i++)
            v2[i] = __hfma2(coef, o2[i], v2[i]);

        a2 = __hfma2(nt2, g2, a2);               // alpha' = alpha - t*gamma
        f2  = __hmul2(f2, rq2);                  // f *= c
        rf2 = __hmul2(rf2, __hmul2(q2, rq2));    // rf *= 1/c

        partner += 2;
        if (partner >= 25) partner -= 25;
    };

    // ---- packed one-sided Jacobi: 25 rounds/sweep = 6 groups of 4 + 1 ----
    for (int sweep = 0; sweep < NSWEEP; sweep++) {
        partner = partner0;
        #pragma unroll 1
        for (int g = 0; g < 6; g++) {
            round_body(); round_body(); round_body(); round_body();
            // renorm once per 4 rounds: f >= 0.0625 guaranteed between checks
            if (__low2float(f2) < 0.25f || __high2float(f2) < 0.25f) {
                #pragma unroll
                for (int i = 0; i < 25; i++) v2[i] = __hmul2(v2[i], f2);
                f2 = ONE2;
                rf2 = ONE2;
            }
        }
        round_body();
        // sweep end: fold scale; (half) alpha refresh kills drift
        #pragma unroll
        for (int i = 0; i < 25; i++) v2[i] = __hmul2(v2[i], f2);
        f2 = ONE2;
        rf2 = ONE2;
        if (sweep != NSWEEP - 1) {
            __half2 acc0 = ZERO2, acc1 = ZERO2;
            #pragma unroll
            for (int i = 0; i < 12; i++) acc0 = __hfma2(v2[i], v2[i], acc0);
            #pragma unroll
            for (int i = 12; i < 25; i++) acc1 = __hfma2(v2[i], v2[i], acc1);
            a2 = __hadd2(acc0, acc1);
        }
    }

    // ---- final norms in fp32 (scale back by 64) ----
    float aA = 0.f, aB = 0.f;
    #pragma unroll
    for (int i = 0; i < 25; i++) {
        float2 cf = __half22float2(v2[i]);
        aA = fmaf(cf.x, cf.x, aA);
        aB = fmaf(cf.y, cf.y, aB);
    }
    aA *= 64.f; aB *= 64.f;

    float acA = fmaxf(aA, 1e-12f), acB = fmaxf(aB, 1e-12f);
    // Sum S^2 from fp32 prologue alphas (trace invariance) — not from fp16 Jacobi.
    float suma = act25 ? (alA + alB) : 0.f;
    float sums = act25 ? (sqrtf(aA) + sqrtf(aB)) : 0.f;
    float mxa  = act25 ? fmaxf(acA, acB) : 0.f;
    float mna  = act25 ? fminf(acA, acB) : 3.0e38f;

    #pragma unroll
    for (int off = 16; off > 0; off >>= 1) {
        suma += __shfl_xor_sync(FULL, suma, off);
        sums += __shfl_xor_sync(FULL, sums, off);
        froA += __shfl_xor_sync(FULL, froA, off);
        froB += __shfl_xor_sync(FULL, froB, off);
        absO += __shfl_xor_sync(FULL, absO, off);
        mxa = fmaxf(mxa, __shfl_xor_sync(FULL, mxa, off));
        mna = fminf(mna, __shfl_xor_sync(FULL, mna, off));
    }
    if (lane == 0) {
        redd[w][0] = (double)suma;
        redd[w][1] = (double)sums;
        redd[w][2] = (double)(sqrtf(froA) + sqrtf(froB));
        redd[w][3] = (double)absO;
        redmx[w] = mxa;
        redmn[w] = mna;
    }
    __syncthreads();

    if (threadIdx.x == 0) {
        double s0 = 0.0, s1 = 0.0, s2 = 0.0, s3 = 0.0;
        float mx = 0.f, mn = 3.0e38f;
        #pragma unroll
        for (int i = 0; i < NWARPS; i++) {
            s0 += redd[i][0]; s1 += redd[i][1]; s2 += redd[i][2]; s3 += redd[i][3];
            mx = fmaxf(mx, redmx[i]);
            mn = fminf(mn, redmn[i]);
        }
        g_pd[blockIdx.x][0] = s0;
        g_pd[blockIdx.x][1] = s1;
        g_pd[blockIdx.x][2] = s2;
        g_pd[blockIdx.x][3] = s3;
        g_pmx[blockIdx.x] = mx;
        g_pmn[blockIdx.x] = mn;
    }
}

#define FTH 1024
__global__ __launch_bounds__(FTH)
void cond_final_kernel(float* __restrict__ out) {
    __shared__ double sd[FTH][4];
    __shared__ float  smx[FTH];
    __shared__ float  smn[FTH];

    const int t = threadIdx.x;
    double a0 = 0.0, a1 = 0.0, a2 = 0.0, a3 = 0.0;
    float mx = 0.f, mn = 3.0e38f;
    for (int i = t; i < NBLOCKS; i += FTH) {
        a0 += g_pd[i][0]; a1 += g_pd[i][1]; a2 += g_pd[i][2]; a3 += g_pd[i][3];
        mx = fmaxf(mx, g_pmx[i]);
        mn = fminf(mn, g_pmn[i]);
    }
    sd[t][0] = a0; sd[t][1] = a1; sd[t][2] = a2; sd[t][3] = a3;
    smx[t] = mx; smn[t] = mn;
    __syncthreads();

    for (int off = FTH / 2; off > 0; off >>= 1) {
        if (t < off) {
            sd[t][0] += sd[t + off][0];
            sd[t][1] += sd[t + off][1];
            sd[t][2] += sd[t + off][2];
            sd[t][3] += sd[t + off][3];
            smx[t] = fmaxf(smx[t], smx[t + off]);
            smn[t] = fminf(smn[t], smn[t + off]);
        }
        __syncthreads();
    }

    if (t == 0) {
        double maxe = (double)smx[0];   // max S^2
        double mine = (double)smn[0];   // min S^2
        const double NB = (double)BATCH * 25.0;
        double loss = (sd[0][2] / (double)BATCH) * 1e-5              // INV * mean fro
                    + (sd[0][0] / NB - 2.0 * (sd[0][1] / NB) + 1.0)  // DEV * mean (S-1)^2
                    + 0.5 * (log(maxe) - log(mine)) * 0.01           // COND
                    + 1e-6 * sd[0][3];                               // L1 * sum|outp|
        out[0] = (float)loss;
    }
}

extern "C" void kernel_launch(void* const* d_in, const int* in_sizes, int n_in,
                              void* d_out, int out_size) {
    const float* inp  = (const float*)d_in[0];
    const float* outp = (const float*)d_in[1];
    float* out = (float*)d_out;
    (void)in_sizes; (void)n_in; (void)out_size;

    cond_main_kernel<<<NBLOCKS, THREADS>>>(inp, outp);
    cond_final_kernel<<<1, FTH>>>(out);
}